// round 4
// baseline (speedup 1.0000x reference)
#include <cuda_runtime.h>
#include <cuda_bf16.h>
#include <mma.h>

using namespace nvcuda;

#define MAXN 50000
#define MAXE 800000

// ---------------- scratch (device globals; no allocation allowed) ----------
__device__ float g_xl[MAXN * 128];     // source transform  [N,128]
__device__ float g_xr[MAXN * 128];     // target transform  [N,128]
__device__ float g_h [MAXN * 128];     // layer output / next activation
__device__ int   g_deg[MAXN];          // degree counts, then scatter cursors
__device__ int   g_rowptr[MAXN + 1];
__device__ int   g_blocksum[64];
__device__ int   g_csr_src[MAXE];      // src node per CSR slot (real edges only)

// ================= CSR build (by dst) ======================================
__global__ void deg_zero(int n) {
    int i = blockIdx.x * blockDim.x + threadIdx.x;
    if (i < n) g_deg[i] = 0;
}

__global__ void deg_count(const int* __restrict__ ei, int E) {
    int i = blockIdx.x * blockDim.x + threadIdx.x;
    if (i < E) atomicAdd(&g_deg[__ldg(&ei[E + i])], 1);
}

__global__ void scan1(int n) {
    __shared__ int s[1024];
    int i = blockIdx.x * 1024 + threadIdx.x;
    int v = (i < n) ? g_deg[i] : 0;
    s[threadIdx.x] = v;
    __syncthreads();
    #pragma unroll
    for (int off = 1; off < 1024; off <<= 1) {
        int t = (threadIdx.x >= off) ? s[threadIdx.x - off] : 0;
        __syncthreads();
        s[threadIdx.x] += t;
        __syncthreads();
    }
    if (i < n) g_rowptr[i] = s[threadIdx.x] - v;           // exclusive
    if (threadIdx.x == 1023) g_blocksum[blockIdx.x] = s[1023];
}

__global__ void scan2(int nb) {                            // 64-thread scan
    __shared__ int s[64];
    int i = threadIdx.x;
    int v = (i < nb) ? g_blocksum[i] : 0;
    s[i] = v;
    __syncthreads();
    #pragma unroll
    for (int off = 1; off < 64; off <<= 1) {
        int t = (i >= off) ? s[i - off] : 0;
        __syncthreads();
        s[i] += t;
        __syncthreads();
    }
    if (i < nb) g_blocksum[i] = s[i] - v;                  // exclusive
}

__global__ void scan3(int n, int E) {
    int i = blockIdx.x * blockDim.x + threadIdx.x;
    if (i < n) {
        g_rowptr[i] += g_blocksum[i >> 10];
        g_deg[i] = 0;                                      // reuse as cursor
    }
    if (i == 0) g_rowptr[n] = E;
}

__global__ void scatter(const int* __restrict__ ei, int E) {
    int i = blockIdx.x * blockDim.x + threadIdx.x;
    if (i >= E) return;
    int s = __ldg(&ei[i]);
    int d = __ldg(&ei[E + i]);
    int pos = g_rowptr[d] + atomicAdd(&g_deg[d], 1);
    g_csr_src[pos] = s;
}

// ============ dual GEMM via bf16 x3 tensor cores ===========================
// xl = A @ Wl, xr = A @ Wr.  Block tile 64 rows x 128 cols (full N).
// 8 warps: warp w -> output (w&1: xr/xl), row tile (w>>1)*16.
// Split precision: v = hi(bf16) + lo(bf16 of residual);
// a*b ~= ah*bh + ah*bl + al*bh   (error ~2^-16, fp32-class).
#define BK 32

using fA = wmma::fragment<wmma::matrix_a, 16, 16, 16, __nv_bfloat16, wmma::row_major>;
using fB = wmma::fragment<wmma::matrix_b, 16, 16, 16, __nv_bfloat16, wmma::row_major>;
using fC = wmma::fragment<wmma::accumulator, 16, 16, 16, float>;

__global__ void dual_gemm_bf16(const float* __restrict__ Aext,
                               const float* __restrict__ Wl,
                               const float* __restrict__ Wr,
                               int useH, int n) {
    __shared__ __nv_bfloat16 Ah[64][BK],  Al[64][BK];
    __shared__ __nv_bfloat16 Wh[2][BK][128], Wo[2][BK][128];
    const float* A = useH ? g_h : Aext;
    const float* Wmat[2] = {Wl, Wr};

    int tid   = threadIdx.x;
    int warp  = tid >> 5;
    int sel   = warp & 1;
    int rtile = warp >> 1;
    int row0  = blockIdx.x * 64;
    int wrow0 = row0 + rtile * 16;

    fC acc[8];
    #pragma unroll
    for (int i = 0; i < 8; ++i) wmma::fill_fragment(acc[i], 0.0f);

    for (int kk = 0; kk < 128; kk += BK) {
        // ---- stage A chunk 64x32 (512 float4, 2/thread) ----
        #pragma unroll
        for (int t = 0; t < 2; ++t) {
            int f  = tid + t * 256;
            int r  = f >> 3;
            int c4 = (f & 7) * 4;
            float4 v = make_float4(0.f, 0.f, 0.f, 0.f);
            if (row0 + r < n)
                v = *(const float4*)&A[(size_t)(row0 + r) * 128 + kk + c4];
            __nv_bfloat16 h0 = __float2bfloat16(v.x);
            __nv_bfloat16 h1 = __float2bfloat16(v.y);
            __nv_bfloat16 h2 = __float2bfloat16(v.z);
            __nv_bfloat16 h3 = __float2bfloat16(v.w);
            *(__nv_bfloat162*)&Ah[r][c4]     = __halves2bfloat162(h0, h1);
            *(__nv_bfloat162*)&Ah[r][c4 + 2] = __halves2bfloat162(h2, h3);
            *(__nv_bfloat162*)&Al[r][c4]     = __halves2bfloat162(
                __float2bfloat16(v.x - __bfloat162float(h0)),
                __float2bfloat16(v.y - __bfloat162float(h1)));
            *(__nv_bfloat162*)&Al[r][c4 + 2] = __halves2bfloat162(
                __float2bfloat16(v.z - __bfloat162float(h2)),
                __float2bfloat16(v.w - __bfloat162float(h3)));
        }
        // ---- stage W chunks 32x128 for both matrices (1024 float4 each) ----
        #pragma unroll
        for (int m = 0; m < 2; ++m) {
            #pragma unroll
            for (int t = 0; t < 4; ++t) {
                int f  = tid + t * 256;
                int r  = f >> 5;
                int c4 = (f & 31) * 4;
                float4 v = *(const float4*)&Wmat[m][(size_t)(kk + r) * 128 + c4];
                __nv_bfloat16 h0 = __float2bfloat16(v.x);
                __nv_bfloat16 h1 = __float2bfloat16(v.y);
                __nv_bfloat16 h2 = __float2bfloat16(v.z);
                __nv_bfloat16 h3 = __float2bfloat16(v.w);
                *(__nv_bfloat162*)&Wh[m][r][c4]     = __halves2bfloat162(h0, h1);
                *(__nv_bfloat162*)&Wh[m][r][c4 + 2] = __halves2bfloat162(h2, h3);
                *(__nv_bfloat162*)&Wo[m][r][c4]     = __halves2bfloat162(
                    __float2bfloat16(v.x - __bfloat162float(h0)),
                    __float2bfloat16(v.y - __bfloat162float(h1)));
                *(__nv_bfloat162*)&Wo[m][r][c4 + 2] = __halves2bfloat162(
                    __float2bfloat16(v.z - __bfloat162float(h2)),
                    __float2bfloat16(v.w - __bfloat162float(h3)));
            }
        }
        __syncthreads();

        #pragma unroll
        for (int ks = 0; ks < BK; ks += 16) {
            fA ah, al;
            wmma::load_matrix_sync(ah, &Ah[rtile * 16][ks], BK);
            wmma::load_matrix_sync(al, &Al[rtile * 16][ks], BK);
            #pragma unroll
            for (int nt = 0; nt < 8; ++nt) {
                fB bh, bl;
                wmma::load_matrix_sync(bh, &Wh[sel][ks][nt * 16], 128);
                wmma::load_matrix_sync(bl, &Wo[sel][ks][nt * 16], 128);
                wmma::mma_sync(acc[nt], ah, bh, acc[nt]);
                wmma::mma_sync(acc[nt], ah, bl, acc[nt]);
                wmma::mma_sync(acc[nt], al, bh, acc[nt]);
            }
        }
        __syncthreads();
    }

    float* C = sel ? g_xr : g_xl;
    if (wrow0 < n) {                     // n % 16 == 0: tile all-or-nothing
        #pragma unroll
        for (int nt = 0; nt < 8; ++nt)
            wmma::store_matrix_sync(&C[(size_t)wrow0 * 128 + nt * 16], acc[nt],
                                    128, wmma::mem_row_major);
    }
}

// ================= fused GAT layer: warp per dst node ======================
__device__ __forceinline__ float edge_p(float4 l4, float4 r4, float4 a4) {
    float v0 = l4.x + r4.x; v0 = v0 > 0.f ? v0 : 0.2f * v0;
    float v1 = l4.y + r4.y; v1 = v1 > 0.f ? v1 : 0.2f * v1;
    float v2 = l4.z + r4.z; v2 = v2 > 0.f ? v2 : 0.2f * v2;
    float v3 = l4.w + r4.w; v3 = v3 > 0.f ? v3 : 0.2f * v3;
    float part = v0 * a4.x + v1 * a4.y + v2 * a4.z + v3 * a4.w;
    part += __shfl_xor_sync(0xffffffffu, part, 1);
    part += __shfl_xor_sync(0xffffffffu, part, 2);
    return __expf(part);
}

__global__ void gat_layer(const float* __restrict__ att,
                          const float* __restrict__ bias,
                          int doRelu, int n) {
    int d = blockIdx.x * 8 + (threadIdx.x >> 5);
    if (d >= n) return;
    int lane = threadIdx.x & 31;

    float4 a4 = *(const float4*)&att[lane * 4];
    float4 r4 = *(const float4*)&g_xr[(size_t)d * 128 + lane * 4];

    // self loop
    float4 l4 = *(const float4*)&g_xl[(size_t)d * 128 + lane * 4];
    float p = edge_p(l4, r4, a4);
    float4 acc = make_float4(p * l4.x, p * l4.y, p * l4.z, p * l4.w);
    float den = p;

    int e   = g_rowptr[d];
    int end = g_rowptr[d + 1];
    // 2-deep software pipeline: idx + gather in flight
    int s2 = (e + 1 < end) ? g_csr_src[e + 1] : 0;
    float4 cur = make_float4(0.f, 0.f, 0.f, 0.f);
    if (e < end)
        cur = *(const float4*)&g_xl[(size_t)g_csr_src[e] * 128 + lane * 4];
    for (; e < end; ++e) {
        float4 nxt = cur;
        if (e + 1 < end)
            nxt = *(const float4*)&g_xl[(size_t)s2 * 128 + lane * 4];
        int s3 = (e + 2 < end) ? g_csr_src[e + 2] : 0;
        p = edge_p(cur, r4, a4);
        acc.x += p * cur.x; acc.y += p * cur.y;
        acc.z += p * cur.z; acc.w += p * cur.w;
        den += p;
        cur = nxt; s2 = s3;
    }

    float inv = 1.0f / (den + 1e-16f);
    float4 b4 = bias ? *(const float4*)&bias[lane * 4]
                     : make_float4(0.f, 0.f, 0.f, 0.f);
    float4 o;
    o.x = acc.x * inv + b4.x;
    o.y = acc.y * inv + b4.y;
    o.z = acc.z * inv + b4.z;
    o.w = acc.w * inv + b4.w;
    if (doRelu) {
        o.x = o.x > 0.f ? o.x : 0.f;
        o.y = o.y > 0.f ? o.y : 0.f;
        o.z = o.z > 0.f ? o.z : 0.f;
        o.w = o.w > 0.f ? o.w : 0.f;
    }
    *(float4*)&g_h[(size_t)d * 128 + lane * 4] = o;
}

// ================= final fc: out = relu(g_h + b2) @ Wfc + bfc ==============
__global__ void fc_out(const float* __restrict__ Wfc,
                       const float* __restrict__ bfc,
                       const float* __restrict__ b2,
                       float* __restrict__ out, int n) {
    __shared__ float Ws[128 * 10];
    __shared__ float bs[10];
    __shared__ float b2s[128];
    for (int i = threadIdx.x; i < 1280; i += blockDim.x) Ws[i] = Wfc[i];
    if (threadIdx.x < 10)  bs[threadIdx.x]  = bfc[threadIdx.x];
    if (threadIdx.x < 128) b2s[threadIdx.x] = b2[threadIdx.x];
    __syncthreads();
    int idx = blockIdx.x * blockDim.x + threadIdx.x;
    if (idx >= n * 10) return;
    int node = idx / 10;
    int c    = idx % 10;
    const float* hrow = &g_h[(size_t)node * 128];
    float acc = bs[c];
    #pragma unroll
    for (int k = 0; k < 128; ++k) {
        float hv = hrow[k] + b2s[k];
        hv = hv > 0.f ? hv : 0.f;
        acc += hv * Ws[k * 10 + c];
    }
    out[idx] = acc;
}

// ================= launch ==================================================
extern "C" void kernel_launch(void* const* d_in, const int* in_sizes, int n_in,
                              void* d_out, int out_size) {
    const float* x    = (const float*)d_in[0];
    const int*   ei   = (const int*)  d_in[1];
    const float* Wl1  = (const float*)d_in[2];
    const float* Wr1  = (const float*)d_in[3];
    const float* att1 = (const float*)d_in[4];
    const float* b1   = (const float*)d_in[5];
    const float* Wl2  = (const float*)d_in[6];
    const float* Wr2  = (const float*)d_in[7];
    const float* att2 = (const float*)d_in[8];
    const float* b2   = (const float*)d_in[9];
    const float* Wfc  = (const float*)d_in[10];
    const float* bfc  = (const float*)d_in[11];
    float* out = (float*)d_out;

    int n = in_sizes[0] / 128;
    int E = in_sizes[1] / 2;

    int nb_scan     = (n + 1023) / 1024;
    int gemm_blocks = (n + 63) / 64;
    int gat_blocks  = (n + 7) / 8;
    int fc_blocks   = (n * 10 + 255) / 256;
    int e_blocks    = (E + 255) / 256;
    int n_blocks    = (n + 255) / 256;

    // ---- CSR build (reused by both layers) ----
    deg_zero<<<n_blocks, 256>>>(n);
    deg_count<<<e_blocks, 256>>>(ei, E);
    scan1<<<nb_scan, 1024>>>(n);
    scan2<<<1, 64>>>(nb_scan);
    scan3<<<n_blocks, 256>>>(n, E);
    scatter<<<e_blocks, 256>>>(ei, E);

    // ---- layer 1 ----
    dual_gemm_bf16<<<gemm_blocks, 256>>>(x, Wl1, Wr1, 0, n);
    gat_layer<<<gat_blocks, 256>>>(att1, b1, 1, n);

    // ---- layer 2 ----
    dual_gemm_bf16<<<gemm_blocks, 256>>>(nullptr, Wl2, Wr2, 1, n);
    gat_layer<<<gat_blocks, 256>>>(att2, nullptr, 0, n);

    // ---- fc ----
    fc_out<<<fc_blocks, 256>>>(Wfc, bfc, b2, out, n);
}

// round 5
// speedup vs baseline: 1.5792x; 1.5792x over previous
#include <cuda_runtime.h>
#include <cuda_bf16.h>
#include <mma.h>

using namespace nvcuda;

#define MAXN 50000
#define MAXE 800000
#define NSM  148
#define SW   136          // padded smem row stride (bf16 elems)

// ---------------- scratch (device globals; no allocation allowed) ----------
__device__ float g_xl[MAXN * 128];
__device__ float g_xr[MAXN * 128];
__device__ float g_h [MAXN * 128];
__device__ int   g_deg[MAXN];
__device__ int   g_rowptr[MAXN + 1];
__device__ int   g_blocksum[64];
__device__ int   g_csr_src[MAXE];

// ================= CSR build (by dst) ======================================
__global__ void deg_zero(int n) {
    int i = blockIdx.x * blockDim.x + threadIdx.x;
    if (i < n) g_deg[i] = 0;
}

__global__ void deg_count(const int* __restrict__ ei, int E) {
    int i = blockIdx.x * blockDim.x + threadIdx.x;
    if (i < E) atomicAdd(&g_deg[__ldg(&ei[E + i])], 1);
}

__global__ void scan1(int n) {
    __shared__ int s[1024];
    int i = blockIdx.x * 1024 + threadIdx.x;
    int v = (i < n) ? g_deg[i] : 0;
    s[threadIdx.x] = v;
    __syncthreads();
    #pragma unroll
    for (int off = 1; off < 1024; off <<= 1) {
        int t = (threadIdx.x >= off) ? s[threadIdx.x - off] : 0;
        __syncthreads();
        s[threadIdx.x] += t;
        __syncthreads();
    }
    if (i < n) g_rowptr[i] = s[threadIdx.x] - v;
    if (threadIdx.x == 1023) g_blocksum[blockIdx.x] = s[1023];
}

__global__ void scan2(int nb) {
    __shared__ int s[64];
    int i = threadIdx.x;
    int v = (i < nb) ? g_blocksum[i] : 0;
    s[i] = v;
    __syncthreads();
    #pragma unroll
    for (int off = 1; off < 64; off <<= 1) {
        int t = (i >= off) ? s[i - off] : 0;
        __syncthreads();
        s[i] += t;
        __syncthreads();
    }
    if (i < nb) g_blocksum[i] = s[i] - v;
}

__global__ void scan3(int n, int E) {
    int i = blockIdx.x * blockDim.x + threadIdx.x;
    if (i < n) {
        g_rowptr[i] += g_blocksum[i >> 10];
        g_deg[i] = 0;
    }
    if (i == 0) g_rowptr[n] = E;
}

__global__ void scatter(const int* __restrict__ ei, int E) {
    int i = blockIdx.x * blockDim.x + threadIdx.x;
    if (i >= E) return;
    int s = __ldg(&ei[i]);
    int d = __ldg(&ei[E + i]);
    int pos = g_rowptr[d] + atomicAdd(&g_deg[d], 1);
    g_csr_src[pos] = s;
}

// ============ persistent dual GEMM via bf16 x3 tensor cores ================
// xl = A@Wl, xr = A@Wr. 148 persistent blocks; W (both mats, hi+lo bf16)
// resident in smem; grid-stride over 64-row A chunks.
// Warp w (of 8): matrix sel = w&1, row tile (w>>1)*16, full 128 cols.
using fA = wmma::fragment<wmma::matrix_a, 16, 16, 16, __nv_bfloat16, wmma::row_major>;
using fB = wmma::fragment<wmma::matrix_b, 16, 16, 16, __nv_bfloat16, wmma::row_major>;
using fC = wmma::fragment<wmma::accumulator, 16, 16, 16, float>;

__device__ __forceinline__ void cvt4(float4 v, __nv_bfloat16* hi, __nv_bfloat16* lo) {
    __nv_bfloat16 h0 = __float2bfloat16(v.x);
    __nv_bfloat16 h1 = __float2bfloat16(v.y);
    __nv_bfloat16 h2 = __float2bfloat16(v.z);
    __nv_bfloat16 h3 = __float2bfloat16(v.w);
    hi[0] = h0; hi[1] = h1; hi[2] = h2; hi[3] = h3;
    lo[0] = __float2bfloat16(v.x - __bfloat162float(h0));
    lo[1] = __float2bfloat16(v.y - __bfloat162float(h1));
    lo[2] = __float2bfloat16(v.z - __bfloat162float(h2));
    lo[3] = __float2bfloat16(v.w - __bfloat162float(h3));
}

extern __shared__ __nv_bfloat16 smem_dg[];
// layout: W[mat][part] at (mat*2+part)*128*SW   (4 * 128*SW)
//         A[part]      at 4*128*SW + part*64*SW (2 *  64*SW)
#define DG_SMEM_BYTES ((4 * 128 * SW + 2 * 64 * SW) * 2)

__global__ void __launch_bounds__(256, 1)
dual_gemm_bf16p(const float* __restrict__ Aext,
                const float* __restrict__ Wl,
                const float* __restrict__ Wr,
                int useH, int n) {
    const float* A = useH ? g_h : Aext;
    const float* Wmat[2] = {Wl, Wr};
    int tid   = threadIdx.x;
    int warp  = tid >> 5;
    int sel   = warp & 1;
    int rtile = warp >> 1;

    __nv_bfloat16* Wbase = smem_dg;
    __nv_bfloat16* Abase = smem_dg + 4 * 128 * SW;

    // ---- stage both W matrices (hi/lo) once ----
    #pragma unroll
    for (int m = 0; m < 2; ++m) {
        __nv_bfloat16* wh = Wbase + (m * 2 + 0) * 128 * SW;
        __nv_bfloat16* wl = Wbase + (m * 2 + 1) * 128 * SW;
        #pragma unroll
        for (int t = 0; t < 16; ++t) {
            int f  = tid + t * 256;          // 0..4095 float4
            int r  = f >> 5;                 // 0..127
            int c4 = (f & 31) * 4;
            float4 v = *(const float4*)&Wmat[m][(size_t)r * 128 + c4];
            cvt4(v, &wh[r * SW + c4], &wl[r * SW + c4]);
        }
    }
    __syncthreads();

    const __nv_bfloat16* wh = Wbase + (sel * 2 + 0) * 128 * SW;
    const __nv_bfloat16* wl = Wbase + (sel * 2 + 1) * 128 * SW;
    __nv_bfloat16* ah_s = Abase;
    __nv_bfloat16* al_s = Abase + 64 * SW;
    float* C = sel ? g_xr : g_xl;

    int nchunks = (n + 63) >> 6;
    for (int c = blockIdx.x; c < nchunks; c += gridDim.x) {
        int row0 = c * 64;
        // ---- stage A chunk 64x128 -> bf16 hi/lo ----
        #pragma unroll
        for (int t = 0; t < 8; ++t) {
            int f  = tid + t * 256;          // 0..2047 float4
            int r  = f >> 5;                 // 0..63
            int c4 = (f & 31) * 4;
            float4 v = make_float4(0.f, 0.f, 0.f, 0.f);
            if (row0 + r < n)
                v = *(const float4*)&A[(size_t)(row0 + r) * 128 + c4];
            cvt4(v, &ah_s[r * SW + c4], &al_s[r * SW + c4]);
        }
        __syncthreads();

        // ---- A fragments into registers (8 k-steps, hi+lo) ----
        fA afh[8], afl[8];
        #pragma unroll
        for (int k = 0; k < 8; ++k) {
            wmma::load_matrix_sync(afh[k], &ah_s[rtile * 16 * SW + k * 16], SW);
            wmma::load_matrix_sync(afl[k], &al_s[rtile * 16 * SW + k * 16], SW);
        }

        fC acc[8];
        #pragma unroll
        for (int i = 0; i < 8; ++i) wmma::fill_fragment(acc[i], 0.0f);

        #pragma unroll
        for (int nt = 0; nt < 8; ++nt) {
            #pragma unroll
            for (int k = 0; k < 8; ++k) {
                fB bh, bl;
                wmma::load_matrix_sync(bh, &wh[k * 16 * SW + nt * 16], SW);
                wmma::load_matrix_sync(bl, &wl[k * 16 * SW + nt * 16], SW);
                wmma::mma_sync(acc[nt], afh[k], bh, acc[nt]);
                wmma::mma_sync(acc[nt], afh[k], bl, acc[nt]);
                wmma::mma_sync(acc[nt], afl[k], bh, acc[nt]);
            }
        }

        int wrow0 = row0 + rtile * 16;
        if (wrow0 < n) {                     // n % 16 == 0
            #pragma unroll
            for (int nt = 0; nt < 8; ++nt)
                wmma::store_matrix_sync(&C[(size_t)wrow0 * 128 + nt * 16],
                                        acc[nt], 128, wmma::mem_row_major);
        }
        __syncthreads();                      // A smem reuse next chunk
    }
}

// ================= fused GAT layer: warp per dst node ======================
__device__ __forceinline__ float edge_p(float4 l4, float4 r4, float4 a4) {
    float v0 = l4.x + r4.x; v0 = v0 > 0.f ? v0 : 0.2f * v0;
    float v1 = l4.y + r4.y; v1 = v1 > 0.f ? v1 : 0.2f * v1;
    float v2 = l4.z + r4.z; v2 = v2 > 0.f ? v2 : 0.2f * v2;
    float v3 = l4.w + r4.w; v3 = v3 > 0.f ? v3 : 0.2f * v3;
    float part = v0 * a4.x + v1 * a4.y + v2 * a4.z + v3 * a4.w;
    part += __shfl_xor_sync(0xffffffffu, part, 1);
    part += __shfl_xor_sync(0xffffffffu, part, 2);
    return __expf(part);
}

__global__ void gat_layer(const float* __restrict__ att,
                          const float* __restrict__ bias,
                          int doRelu, int n) {
    int d = blockIdx.x * 8 + (threadIdx.x >> 5);
    if (d >= n) return;
    int lane = threadIdx.x & 31;

    float4 a4 = *(const float4*)&att[lane * 4];
    float4 r4 = *(const float4*)&g_xr[(size_t)d * 128 + lane * 4];

    float4 l4 = *(const float4*)&g_xl[(size_t)d * 128 + lane * 4];
    float p = edge_p(l4, r4, a4);
    float4 acc = make_float4(p * l4.x, p * l4.y, p * l4.z, p * l4.w);
    float den = p;

    int e   = g_rowptr[d];
    int end = g_rowptr[d + 1];
    int s2 = (e + 1 < end) ? g_csr_src[e + 1] : 0;
    float4 cur = make_float4(0.f, 0.f, 0.f, 0.f);
    if (e < end)
        cur = *(const float4*)&g_xl[(size_t)g_csr_src[e] * 128 + lane * 4];
    for (; e < end; ++e) {
        float4 nxt = cur;
        if (e + 1 < end)
            nxt = *(const float4*)&g_xl[(size_t)s2 * 128 + lane * 4];
        int s3 = (e + 2 < end) ? g_csr_src[e + 2] : 0;
        p = edge_p(cur, r4, a4);
        acc.x += p * cur.x; acc.y += p * cur.y;
        acc.z += p * cur.z; acc.w += p * cur.w;
        den += p;
        cur = nxt; s2 = s3;
    }

    float inv = 1.0f / (den + 1e-16f);
    float4 b4 = bias ? *(const float4*)&bias[lane * 4]
                     : make_float4(0.f, 0.f, 0.f, 0.f);
    float4 o;
    o.x = acc.x * inv + b4.x;
    o.y = acc.y * inv + b4.y;
    o.z = acc.z * inv + b4.z;
    o.w = acc.w * inv + b4.w;
    if (doRelu) {
        o.x = o.x > 0.f ? o.x : 0.f;
        o.y = o.y > 0.f ? o.y : 0.f;
        o.z = o.z > 0.f ? o.z : 0.f;
        o.w = o.w > 0.f ? o.w : 0.f;
    }
    *(float4*)&g_h[(size_t)d * 128 + lane * 4] = o;
}

// ================= final fc: out = relu(g_h + b2) @ Wfc + bfc ==============
__global__ void fc_out(const float* __restrict__ Wfc,
                       const float* __restrict__ bfc,
                       const float* __restrict__ b2,
                       float* __restrict__ out, int n) {
    __shared__ float Ws[128 * 10];
    __shared__ float bs[10];
    __shared__ float b2s[128];
    for (int i = threadIdx.x; i < 1280; i += blockDim.x) Ws[i] = Wfc[i];
    if (threadIdx.x < 10)  bs[threadIdx.x]  = bfc[threadIdx.x];
    if (threadIdx.x < 128) b2s[threadIdx.x] = b2[threadIdx.x];
    __syncthreads();
    int idx = blockIdx.x * blockDim.x + threadIdx.x;
    if (idx >= n * 10) return;
    int node = idx / 10;
    int c    = idx % 10;
    const float* hrow = &g_h[(size_t)node * 128];
    float acc = bs[c];
    #pragma unroll
    for (int k = 0; k < 128; ++k) {
        float hv = hrow[k] + b2s[k];
        hv = hv > 0.f ? hv : 0.f;
        acc += hv * Ws[k * 10 + c];
    }
    out[idx] = acc;
}

// ================= launch ==================================================
extern "C" void kernel_launch(void* const* d_in, const int* in_sizes, int n_in,
                              void* d_out, int out_size) {
    const float* x    = (const float*)d_in[0];
    const int*   ei   = (const int*)  d_in[1];
    const float* Wl1  = (const float*)d_in[2];
    const float* Wr1  = (const float*)d_in[3];
    const float* att1 = (const float*)d_in[4];
    const float* b1   = (const float*)d_in[5];
    const float* Wl2  = (const float*)d_in[6];
    const float* Wr2  = (const float*)d_in[7];
    const float* att2 = (const float*)d_in[8];
    const float* b2   = (const float*)d_in[9];
    const float* Wfc  = (const float*)d_in[10];
    const float* bfc  = (const float*)d_in[11];
    float* out = (float*)d_out;

    int n = in_sizes[0] / 128;
    int E = in_sizes[1] / 2;

    int nb_scan    = (n + 1023) / 1024;
    int gat_blocks = (n + 7) / 8;
    int fc_blocks  = (n * 10 + 255) / 256;
    int e_blocks   = (E + 255) / 256;
    int n_blocks   = (n + 255) / 256;

    static int smem_set = 0;
    if (!smem_set) {
        cudaFuncSetAttribute(dual_gemm_bf16p,
                             cudaFuncAttributeMaxDynamicSharedMemorySize,
                             DG_SMEM_BYTES);
        smem_set = 1;
    }

    // ---- CSR build ----
    deg_zero<<<n_blocks, 256>>>(n);
    deg_count<<<e_blocks, 256>>>(ei, E);
    scan1<<<nb_scan, 1024>>>(n);
    scan2<<<1, 64>>>(nb_scan);
    scan3<<<n_blocks, 256>>>(n, E);
    scatter<<<e_blocks, 256>>>(ei, E);

    // ---- layer 1 ----
    dual_gemm_bf16p<<<NSM, 256, DG_SMEM_BYTES>>>(x, Wl1, Wr1, 0, n);
    gat_layer<<<gat_blocks, 256>>>(att1, b1, 1, n);

    // ---- layer 2 ----
    dual_gemm_bf16p<<<NSM, 256, DG_SMEM_BYTES>>>(nullptr, Wl2, Wr2, 1, n);
    gat_layer<<<gat_blocks, 256>>>(att2, nullptr, 0, n);

    // ---- fc ----
    fc_out<<<fc_blocks, 256>>>(Wfc, bfc, b2, out, n);
}

// round 7
// speedup vs baseline: 1.6985x; 1.0756x over previous
#include <cuda_runtime.h>
#include <cuda_bf16.h>
#include <mma.h>

using namespace nvcuda;

#define MAXN 50000
#define MAXE 800000
#define NSM  148
#define SW   136          // padded smem row stride (bf16 elems)

// ---------------- scratch (device globals; no allocation allowed) ----------
__device__ float g_xl[MAXN * 128];
__device__ float g_xr[MAXN * 128];
__device__ float g_h [MAXN * 128];
__device__ int   g_deg[MAXN];
__device__ int   g_rowptr[MAXN + 1];
__device__ int   g_blocksum[64];
__device__ int   g_csr_src[MAXE];

// ================= CSR build (by dst) ======================================
__global__ void deg_zero(int n) {
    int i = blockIdx.x * blockDim.x + threadIdx.x;
    if (i < n) g_deg[i] = 0;
}

__global__ void deg_count(const int* __restrict__ ei, int E) {
    int i = blockIdx.x * blockDim.x + threadIdx.x;
    if (i < E) atomicAdd(&g_deg[__ldg(&ei[E + i])], 1);
}

__global__ void scan1(int n) {
    __shared__ int s[1024];
    int i = blockIdx.x * 1024 + threadIdx.x;
    int v = (i < n) ? g_deg[i] : 0;
    s[threadIdx.x] = v;
    __syncthreads();
    #pragma unroll
    for (int off = 1; off < 1024; off <<= 1) {
        int t = (threadIdx.x >= off) ? s[threadIdx.x - off] : 0;
        __syncthreads();
        s[threadIdx.x] += t;
        __syncthreads();
    }
    if (i < n) g_rowptr[i] = s[threadIdx.x] - v;            // block-exclusive
    if (threadIdx.x == 1023) g_blocksum[blockIdx.x] = s[1023];
}

// scan3: fold the tiny blocksum scan in (all-thread barriers — cross-warp safe)
__global__ void scan3(int n, int E, int nb) {
    __shared__ int bs[64];
    int tid = threadIdx.x;
    if (tid < 64) bs[tid] = (tid < nb) ? g_blocksum[tid] : 0;
    __syncthreads();
    #pragma unroll
    for (int off = 1; off < 64; off <<= 1) {
        int t = (tid < 64 && tid >= off) ? bs[tid - off] : 0;
        __syncthreads();
        if (tid < 64) bs[tid] += t;
        __syncthreads();
    }
    // bs is now the INCLUSIVE scan of blocksums
    int i = blockIdx.x * blockDim.x + tid;
    if (i < n) {
        int b = i >> 10;
        int pre = (b == 0) ? 0 : bs[b - 1];  // exclusive prefix for block b
        g_rowptr[i] += pre;
        g_deg[i] = 0;                        // reuse as cursor
    }
    if (i == 0) g_rowptr[n] = E;
}

__global__ void scatter(const int* __restrict__ ei, int E) {
    int i = blockIdx.x * blockDim.x + threadIdx.x;
    if (i >= E) return;
    int s = __ldg(&ei[i]);
    int d = __ldg(&ei[E + i]);
    int pos = g_rowptr[d] + atomicAdd(&g_deg[d], 1);
    g_csr_src[pos] = s;
}

// ============ persistent dual GEMM via bf16 x3 tensor cores ================
using fA = wmma::fragment<wmma::matrix_a, 16, 16, 16, __nv_bfloat16, wmma::row_major>;
using fB = wmma::fragment<wmma::matrix_b, 16, 16, 16, __nv_bfloat16, wmma::row_major>;
using fC = wmma::fragment<wmma::accumulator, 16, 16, 16, float>;

__device__ __forceinline__ void cvt4(float4 v, __nv_bfloat16* hi, __nv_bfloat16* lo) {
    __nv_bfloat16 h0 = __float2bfloat16(v.x);
    __nv_bfloat16 h1 = __float2bfloat16(v.y);
    __nv_bfloat16 h2 = __float2bfloat16(v.z);
    __nv_bfloat16 h3 = __float2bfloat16(v.w);
    hi[0] = h0; hi[1] = h1; hi[2] = h2; hi[3] = h3;
    lo[0] = __float2bfloat16(v.x - __bfloat162float(h0));
    lo[1] = __float2bfloat16(v.y - __bfloat162float(h1));
    lo[2] = __float2bfloat16(v.z - __bfloat162float(h2));
    lo[3] = __float2bfloat16(v.w - __bfloat162float(h3));
}

extern __shared__ __nv_bfloat16 smem_dg[];
#define DG_SMEM_BYTES ((4 * 128 * SW + 2 * 64 * SW) * 2)

__global__ void __launch_bounds__(256, 1)
dual_gemm_bf16p(const float* __restrict__ Aext,
                const float* __restrict__ Wl,
                const float* __restrict__ Wr,
                int useH, int n) {
    const float* A = useH ? g_h : Aext;
    const float* Wmat[2] = {Wl, Wr};
    int tid   = threadIdx.x;
    int warp  = tid >> 5;
    int sel   = warp & 1;
    int rtile = warp >> 1;

    __nv_bfloat16* Wbase = smem_dg;
    __nv_bfloat16* Abase = smem_dg + 4 * 128 * SW;

    #pragma unroll
    for (int m = 0; m < 2; ++m) {
        __nv_bfloat16* wh = Wbase + (m * 2 + 0) * 128 * SW;
        __nv_bfloat16* wl = Wbase + (m * 2 + 1) * 128 * SW;
        #pragma unroll
        for (int t = 0; t < 16; ++t) {
            int f  = tid + t * 256;
            int r  = f >> 5;
            int c4 = (f & 31) * 4;
            float4 v = *(const float4*)&Wmat[m][(size_t)r * 128 + c4];
            cvt4(v, &wh[r * SW + c4], &wl[r * SW + c4]);
        }
    }
    __syncthreads();

    const __nv_bfloat16* wh = Wbase + (sel * 2 + 0) * 128 * SW;
    const __nv_bfloat16* wl = Wbase + (sel * 2 + 1) * 128 * SW;
    __nv_bfloat16* ah_s = Abase;
    __nv_bfloat16* al_s = Abase + 64 * SW;
    float* C = sel ? g_xr : g_xl;

    int nchunks = (n + 63) >> 6;
    for (int c = blockIdx.x; c < nchunks; c += gridDim.x) {
        int row0 = c * 64;
        #pragma unroll
        for (int t = 0; t < 8; ++t) {
            int f  = tid + t * 256;
            int r  = f >> 5;
            int c4 = (f & 31) * 4;
            float4 v = make_float4(0.f, 0.f, 0.f, 0.f);
            if (row0 + r < n)
                v = *(const float4*)&A[(size_t)(row0 + r) * 128 + c4];
            cvt4(v, &ah_s[r * SW + c4], &al_s[r * SW + c4]);
        }
        __syncthreads();

        fA afh[8], afl[8];
        #pragma unroll
        for (int k = 0; k < 8; ++k) {
            wmma::load_matrix_sync(afh[k], &ah_s[rtile * 16 * SW + k * 16], SW);
            wmma::load_matrix_sync(afl[k], &al_s[rtile * 16 * SW + k * 16], SW);
        }

        fC acc[8];
        #pragma unroll
        for (int i = 0; i < 8; ++i) wmma::fill_fragment(acc[i], 0.0f);

        #pragma unroll
        for (int nt = 0; nt < 8; ++nt) {
            #pragma unroll
            for (int k = 0; k < 8; ++k) {
                fB bh, bl;
                wmma::load_matrix_sync(bh, &wh[k * 16 * SW + nt * 16], SW);
                wmma::load_matrix_sync(bl, &wl[k * 16 * SW + nt * 16], SW);
                wmma::mma_sync(acc[nt], afh[k], bh, acc[nt]);
                wmma::mma_sync(acc[nt], afh[k], bl, acc[nt]);
                wmma::mma_sync(acc[nt], afl[k], bh, acc[nt]);
            }
        }

        int wrow0 = row0 + rtile * 16;
        if (wrow0 < n) {
            #pragma unroll
            for (int nt = 0; nt < 8; ++nt)
                wmma::store_matrix_sync(&C[(size_t)wrow0 * 128 + nt * 16],
                                        acc[nt], 128, wmma::mem_row_major);
        }
        __syncthreads();
    }
}

// ================= fused GAT layer: warp per dst node ======================
__device__ __forceinline__ float edge_p(float4 l4, float4 r4, float4 a4) {
    float v0 = l4.x + r4.x; v0 = v0 > 0.f ? v0 : 0.2f * v0;
    float v1 = l4.y + r4.y; v1 = v1 > 0.f ? v1 : 0.2f * v1;
    float v2 = l4.z + r4.z; v2 = v2 > 0.f ? v2 : 0.2f * v2;
    float v3 = l4.w + r4.w; v3 = v3 > 0.f ? v3 : 0.2f * v3;
    float part = v0 * a4.x + v1 * a4.y + v2 * a4.z + v3 * a4.w;
    part += __shfl_xor_sync(0xffffffffu, part, 1);
    part += __shfl_xor_sync(0xffffffffu, part, 2);
    return __expf(part);
}

__global__ void gat_layer(const float* __restrict__ att,
                          const float* __restrict__ bias,
                          int doRelu, int n) {
    int d = blockIdx.x * 8 + (threadIdx.x >> 5);
    if (d >= n) return;
    int lane = threadIdx.x & 31;

    float4 a4 = *(const float4*)&att[lane * 4];
    float4 r4 = *(const float4*)&g_xr[(size_t)d * 128 + lane * 4];

    // self loop
    float4 l4 = *(const float4*)&g_xl[(size_t)d * 128 + lane * 4];
    float p = edge_p(l4, r4, a4);
    float4 acc = make_float4(p * l4.x, p * l4.y, p * l4.z, p * l4.w);
    float den = p;

    int e   = g_rowptr[d];
    int end = g_rowptr[d + 1];

    // unrolled x2: two independent gathers in flight per iteration
    for (; e + 1 < end; e += 2) {
        int s0 = __ldg(&g_csr_src[e]);
        int s1 = __ldg(&g_csr_src[e + 1]);
        float4 u0 = *(const float4*)&g_xl[(size_t)s0 * 128 + lane * 4];
        float4 u1 = *(const float4*)&g_xl[(size_t)s1 * 128 + lane * 4];
        float p0 = edge_p(u0, r4, a4);
        float p1 = edge_p(u1, r4, a4);
        acc.x += p0 * u0.x + p1 * u1.x;
        acc.y += p0 * u0.y + p1 * u1.y;
        acc.z += p0 * u0.z + p1 * u1.z;
        acc.w += p0 * u0.w + p1 * u1.w;
        den += p0 + p1;
    }
    if (e < end) {
        int s0 = __ldg(&g_csr_src[e]);
        float4 u0 = *(const float4*)&g_xl[(size_t)s0 * 128 + lane * 4];
        float p0 = edge_p(u0, r4, a4);
        acc.x += p0 * u0.x; acc.y += p0 * u0.y;
        acc.z += p0 * u0.z; acc.w += p0 * u0.w;
        den += p0;
    }

    float inv = 1.0f / (den + 1e-16f);
    float4 b4 = bias ? *(const float4*)&bias[lane * 4]
                     : make_float4(0.f, 0.f, 0.f, 0.f);
    float4 o;
    o.x = acc.x * inv + b4.x;
    o.y = acc.y * inv + b4.y;
    o.z = acc.z * inv + b4.z;
    o.w = acc.w * inv + b4.w;
    if (doRelu) {
        o.x = o.x > 0.f ? o.x : 0.f;
        o.y = o.y > 0.f ? o.y : 0.f;
        o.z = o.z > 0.f ? o.z : 0.f;
        o.w = o.w > 0.f ? o.w : 0.f;
    }
    *(float4*)&g_h[(size_t)d * 128 + lane * 4] = o;
}

// ================= final fc: out = relu(g_h + b2) @ Wfc + bfc ==============
__global__ void fc_out(const float* __restrict__ Wfc,
                       const float* __restrict__ bfc,
                       const float* __restrict__ b2,
                       float* __restrict__ out, int n) {
    __shared__ float Ws[128 * 10];
    __shared__ float bs[10];
    __shared__ float b2s[128];
    for (int i = threadIdx.x; i < 1280; i += blockDim.x) Ws[i] = Wfc[i];
    if (threadIdx.x < 10)  bs[threadIdx.x]  = bfc[threadIdx.x];
    if (threadIdx.x < 128) b2s[threadIdx.x] = b2[threadIdx.x];
    __syncthreads();
    int idx = blockIdx.x * blockDim.x + threadIdx.x;
    if (idx >= n * 10) return;
    int node = idx / 10;
    int c    = idx % 10;
    const float* hrow = &g_h[(size_t)node * 128];
    float acc = bs[c];
    #pragma unroll
    for (int k = 0; k < 128; ++k) {
        float hv = hrow[k] + b2s[k];
        hv = hv > 0.f ? hv : 0.f;
        acc += hv * Ws[k * 10 + c];
    }
    out[idx] = acc;
}

// ================= launch ==================================================
extern "C" void kernel_launch(void* const* d_in, const int* in_sizes, int n_in,
                              void* d_out, int out_size) {
    const float* x    = (const float*)d_in[0];
    const int*   ei   = (const int*)  d_in[1];
    const float* Wl1  = (const float*)d_in[2];
    const float* Wr1  = (const float*)d_in[3];
    const float* att1 = (const float*)d_in[4];
    const float* b1   = (const float*)d_in[5];
    const float* Wl2  = (const float*)d_in[6];
    const float* Wr2  = (const float*)d_in[7];
    const float* att2 = (const float*)d_in[8];
    const float* b2   = (const float*)d_in[9];
    const float* Wfc  = (const float*)d_in[10];
    const float* bfc  = (const float*)d_in[11];
    float* out = (float*)d_out;

    int n = in_sizes[0] / 128;
    int E = in_sizes[1] / 2;

    int nb_scan    = (n + 1023) / 1024;
    int gat_blocks = (n + 7) / 8;
    int fc_blocks  = (n * 10 + 255) / 256;
    int e_blocks   = (E + 255) / 256;
    int n_blocks   = (n + 255) / 256;

    // one-time setup on the uncaptured correctness call
    static int inited = 0;
    static cudaStream_t s_csr;
    static cudaEvent_t  ev_fork, ev_join;
    if (!inited) {
        cudaFuncSetAttribute(dual_gemm_bf16p,
                             cudaFuncAttributeMaxDynamicSharedMemorySize,
                             DG_SMEM_BYTES);
        cudaStreamCreateWithFlags(&s_csr, cudaStreamNonBlocking);
        cudaEventCreateWithFlags(&ev_fork, cudaEventDisableTiming);
        cudaEventCreateWithFlags(&ev_join, cudaEventDisableTiming);
        inited = 1;
    }

    // ---- fork: CSR build (s_csr)  ||  layer-1 GEMM (default) ----
    cudaEventRecord(ev_fork, 0);
    cudaStreamWaitEvent(s_csr, ev_fork, 0);

    deg_zero<<<n_blocks, 256, 0, s_csr>>>(n);
    deg_count<<<e_blocks, 256, 0, s_csr>>>(ei, E);
    scan1<<<nb_scan, 1024, 0, s_csr>>>(n);
    scan3<<<n_blocks, 256, 0, s_csr>>>(n, E, nb_scan);
    scatter<<<e_blocks, 256, 0, s_csr>>>(ei, E);
    cudaEventRecord(ev_join, s_csr);

    dual_gemm_bf16p<<<NSM, 256, DG_SMEM_BYTES>>>(x, Wl1, Wr1, 0, n);

    cudaStreamWaitEvent(0, ev_join, 0);     // join before gat_layer

    // ---- layer 1 ----
    gat_layer<<<gat_blocks, 256>>>(att1, b1, 1, n);

    // ---- layer 2 ----
    dual_gemm_bf16p<<<NSM, 256, DG_SMEM_BYTES>>>(nullptr, Wl2, Wr2, 1, n);
    gat_layer<<<gat_blocks, 256>>>(att2, nullptr, 0, n);

    // ---- fc ----
    fc_out<<<fc_blocks, 256>>>(Wfc, bfc, b2, out, n);
}

// round 8
// speedup vs baseline: 1.7020x; 1.0020x over previous
#include <cuda_runtime.h>
#include <cuda_bf16.h>
#include <cuda_fp16.h>
#include <mma.h>

using namespace nvcuda;

#define MAXN 50000
#define MAXE 800000
#define NSM  148
#define SW   136          // padded smem row stride (bf16 elems)

// ---------------- scratch (device globals; no allocation allowed) ----------
__device__ __half g_xlh[MAXN * 128];   // source transform, fp16 (messages)
__device__ float  g_xr [MAXN * 128];   // target transform, fp32
__device__ float  g_h  [MAXN * 128];   // layer output / next activation
__device__ int    g_deg[MAXN];
__device__ int    g_rowptr[MAXN + 1];
__device__ int    g_blocksum[64];
__device__ int    g_csr_src[MAXE];

// ================= CSR build (by dst) ======================================
__global__ void deg_zero(int n) {
    int i = blockIdx.x * blockDim.x + threadIdx.x;
    if (i < n) g_deg[i] = 0;
}

__global__ void deg_count(const int* __restrict__ ei, int E) {
    int i = blockIdx.x * blockDim.x + threadIdx.x;
    if (i < E) atomicAdd(&g_deg[__ldg(&ei[E + i])], 1);
}

__global__ void scan1(int n) {
    __shared__ int s[1024];
    int i = blockIdx.x * 1024 + threadIdx.x;
    int v = (i < n) ? g_deg[i] : 0;
    s[threadIdx.x] = v;
    __syncthreads();
    #pragma unroll
    for (int off = 1; off < 1024; off <<= 1) {
        int t = (threadIdx.x >= off) ? s[threadIdx.x - off] : 0;
        __syncthreads();
        s[threadIdx.x] += t;
        __syncthreads();
    }
    if (i < n) g_rowptr[i] = s[threadIdx.x] - v;            // block-exclusive
    if (threadIdx.x == 1023) g_blocksum[blockIdx.x] = s[1023];
}

// scan3: folded blocksum scan (all-thread barriers — cross-warp safe)
__global__ void scan3(int n, int E, int nb) {
    __shared__ int bs[64];
    int tid = threadIdx.x;
    if (tid < 64) bs[tid] = (tid < nb) ? g_blocksum[tid] : 0;
    __syncthreads();
    #pragma unroll
    for (int off = 1; off < 64; off <<= 1) {
        int t = (tid < 64 && tid >= off) ? bs[tid - off] : 0;
        __syncthreads();
        if (tid < 64) bs[tid] += t;
        __syncthreads();
    }
    int i = blockIdx.x * blockDim.x + tid;
    if (i < n) {
        int b = i >> 10;
        int pre = (b == 0) ? 0 : bs[b - 1];
        g_rowptr[i] += pre;
        g_deg[i] = 0;
    }
    if (i == 0) g_rowptr[n] = E;
}

__global__ void scatter(const int* __restrict__ ei, int E) {
    int i = blockIdx.x * blockDim.x + threadIdx.x;
    if (i >= E) return;
    int s = __ldg(&ei[i]);
    int d = __ldg(&ei[E + i]);
    int pos = g_rowptr[d] + atomicAdd(&g_deg[d], 1);
    g_csr_src[pos] = s;
}

// ============ persistent dual GEMM via bf16 x3 tensor cores ================
// xl -> g_xlh (fp16, via smem staging), xr -> g_xr (fp32).
using fA = wmma::fragment<wmma::matrix_a, 16, 16, 16, __nv_bfloat16, wmma::row_major>;
using fB = wmma::fragment<wmma::matrix_b, 16, 16, 16, __nv_bfloat16, wmma::row_major>;
using fC = wmma::fragment<wmma::accumulator, 16, 16, 16, float>;

__device__ __forceinline__ void cvt4(float4 v, __nv_bfloat16* hi, __nv_bfloat16* lo) {
    __nv_bfloat16 h0 = __float2bfloat16(v.x);
    __nv_bfloat16 h1 = __float2bfloat16(v.y);
    __nv_bfloat16 h2 = __float2bfloat16(v.z);
    __nv_bfloat16 h3 = __float2bfloat16(v.w);
    hi[0] = h0; hi[1] = h1; hi[2] = h2; hi[3] = h3;
    lo[0] = __float2bfloat16(v.x - __bfloat162float(h0));
    lo[1] = __float2bfloat16(v.y - __bfloat162float(h1));
    lo[2] = __float2bfloat16(v.z - __bfloat162float(h2));
    lo[3] = __float2bfloat16(v.w - __bfloat162float(h3));
}

extern __shared__ __nv_bfloat16 smem_dg[];
#define DG_SMEM_BYTES ((4 * 128 * SW + 2 * 64 * SW) * 2)

__global__ void __launch_bounds__(256, 1)
dual_gemm_bf16p(const float* __restrict__ Aext,
                const float* __restrict__ Wl,
                const float* __restrict__ Wr,
                int useH, int n) {
    const float* A = useH ? g_h : Aext;
    const float* Wmat[2] = {Wl, Wr};
    int tid   = threadIdx.x;
    int warp  = tid >> 5;
    int sel   = warp & 1;
    int rtile = warp >> 1;

    __nv_bfloat16* Wbase = smem_dg;
    __nv_bfloat16* Abase = smem_dg + 4 * 128 * SW;
    float* stg = (float*)Abase;            // 64x128 fp32 staging (32KB <= 34.8KB)

    #pragma unroll
    for (int m = 0; m < 2; ++m) {
        __nv_bfloat16* wh = Wbase + (m * 2 + 0) * 128 * SW;
        __nv_bfloat16* wl = Wbase + (m * 2 + 1) * 128 * SW;
        #pragma unroll
        for (int t = 0; t < 16; ++t) {
            int f  = tid + t * 256;
            int r  = f >> 5;
            int c4 = (f & 31) * 4;
            float4 v = *(const float4*)&Wmat[m][(size_t)r * 128 + c4];
            cvt4(v, &wh[r * SW + c4], &wl[r * SW + c4]);
        }
    }
    __syncthreads();

    const __nv_bfloat16* wh = Wbase + (sel * 2 + 0) * 128 * SW;
    const __nv_bfloat16* wl = Wbase + (sel * 2 + 1) * 128 * SW;
    __nv_bfloat16* ah_s = Abase;
    __nv_bfloat16* al_s = Abase + 64 * SW;

    int nchunks = (n + 63) >> 6;
    for (int c = blockIdx.x; c < nchunks; c += gridDim.x) {
        int row0 = c * 64;
        #pragma unroll
        for (int t = 0; t < 8; ++t) {
            int f  = tid + t * 256;
            int r  = f >> 5;
            int c4 = (f & 31) * 4;
            float4 v = make_float4(0.f, 0.f, 0.f, 0.f);
            if (row0 + r < n)
                v = *(const float4*)&A[(size_t)(row0 + r) * 128 + c4];
            cvt4(v, &ah_s[r * SW + c4], &al_s[r * SW + c4]);
        }
        __syncthreads();

        fA afh[8], afl[8];
        #pragma unroll
        for (int k = 0; k < 8; ++k) {
            wmma::load_matrix_sync(afh[k], &ah_s[rtile * 16 * SW + k * 16], SW);
            wmma::load_matrix_sync(afl[k], &al_s[rtile * 16 * SW + k * 16], SW);
        }

        fC acc[8];
        #pragma unroll
        for (int i = 0; i < 8; ++i) wmma::fill_fragment(acc[i], 0.0f);

        #pragma unroll
        for (int nt = 0; nt < 8; ++nt) {
            #pragma unroll
            for (int k = 0; k < 8; ++k) {
                fB bh, bl;
                wmma::load_matrix_sync(bh, &wh[k * 16 * SW + nt * 16], SW);
                wmma::load_matrix_sync(bl, &wl[k * 16 * SW + nt * 16], SW);
                wmma::mma_sync(acc[nt], afh[k], bh, acc[nt]);
                wmma::mma_sync(acc[nt], afh[k], bl, acc[nt]);
                wmma::mma_sync(acc[nt], afl[k], bh, acc[nt]);
            }
        }
        __syncthreads();          // A frags consumed; smem free for staging

        int wrow0 = row0 + rtile * 16;
        if (sel == 1) {
            // xr: straight fp32 store
            if (wrow0 < n) {
                #pragma unroll
                for (int nt = 0; nt < 8; ++nt)
                    wmma::store_matrix_sync(&g_xr[(size_t)wrow0 * 128 + nt * 16],
                                            acc[nt], 128, wmma::mem_row_major);
            }
        } else {
            // xl: stage fp32 into smem (even out-of-range tiles are fine)
            #pragma unroll
            for (int nt = 0; nt < 8; ++nt)
                wmma::store_matrix_sync(&stg[(size_t)(rtile * 16) * 128 + nt * 16],
                                        acc[nt], 128, wmma::mem_row_major);
        }
        __syncthreads();

        // cooperative fp32->fp16 conversion of the 64x128 xl staging
        #pragma unroll
        for (int t = 0; t < 8; ++t) {
            int f  = tid + t * 256;           // 0..2047 float4
            int r  = f >> 5;
            int c4 = (f & 31) * 4;
            if (row0 + r < n) {
                float4 v = *(const float4*)&stg[r * 128 + c4];
                __half2 a = __floats2half2_rn(v.x, v.y);
                __half2 b = __floats2half2_rn(v.z, v.w);
                uint2 u;
                u.x = *(unsigned*)&a;
                u.y = *(unsigned*)&b;
                *(uint2*)&g_xlh[(size_t)(row0 + r) * 128 + c4] = u;
            }
        }
        __syncthreads();          // staging free before next-chunk A stage
    }
}

// ================= fused GAT layer: warp per dst node ======================
__device__ __forceinline__ float4 ldh4(const __half* p) {
    uint2 u = *(const uint2*)p;
    __half2 h0 = *reinterpret_cast<__half2*>(&u.x);
    __half2 h1 = *reinterpret_cast<__half2*>(&u.y);
    float2 f0 = __half22float2(h0);
    float2 f1 = __half22float2(h1);
    return make_float4(f0.x, f0.y, f1.x, f1.y);
}

__device__ __forceinline__ float edge_p(float4 l4, float4 r4, float4 a4) {
    float v0 = l4.x + r4.x; v0 = v0 > 0.f ? v0 : 0.2f * v0;
    float v1 = l4.y + r4.y; v1 = v1 > 0.f ? v1 : 0.2f * v1;
    float v2 = l4.z + r4.z; v2 = v2 > 0.f ? v2 : 0.2f * v2;
    float v3 = l4.w + r4.w; v3 = v3 > 0.f ? v3 : 0.2f * v3;
    float part = v0 * a4.x + v1 * a4.y + v2 * a4.z + v3 * a4.w;
    part += __shfl_xor_sync(0xffffffffu, part, 1);
    part += __shfl_xor_sync(0xffffffffu, part, 2);
    return __expf(part);
}

__global__ void gat_layer(const float* __restrict__ att,
                          const float* __restrict__ bias,
                          int doRelu, int n) {
    int d = blockIdx.x * 8 + (threadIdx.x >> 5);
    if (d >= n) return;
    int lane = threadIdx.x & 31;

    float4 a4 = *(const float4*)&att[lane * 4];
    float4 r4 = *(const float4*)&g_xr[(size_t)d * 128 + lane * 4];

    // self loop (message read from fp16 like all others)
    float4 l4 = ldh4(&g_xlh[(size_t)d * 128 + lane * 4]);
    float p = edge_p(l4, r4, a4);
    float4 acc = make_float4(p * l4.x, p * l4.y, p * l4.z, p * l4.w);
    float den = p;

    int e   = g_rowptr[d];
    int end = g_rowptr[d + 1];

    // unrolled x4: four independent gathers in flight
    for (; e + 3 < end; e += 4) {
        int s0 = __ldg(&g_csr_src[e]);
        int s1 = __ldg(&g_csr_src[e + 1]);
        int s2 = __ldg(&g_csr_src[e + 2]);
        int s3 = __ldg(&g_csr_src[e + 3]);
        float4 u0 = ldh4(&g_xlh[(size_t)s0 * 128 + lane * 4]);
        float4 u1 = ldh4(&g_xlh[(size_t)s1 * 128 + lane * 4]);
        float4 u2 = ldh4(&g_xlh[(size_t)s2 * 128 + lane * 4]);
        float4 u3 = ldh4(&g_xlh[(size_t)s3 * 128 + lane * 4]);
        float p0 = edge_p(u0, r4, a4);
        float p1 = edge_p(u1, r4, a4);
        float p2 = edge_p(u2, r4, a4);
        float p3 = edge_p(u3, r4, a4);
        acc.x += p0 * u0.x + p1 * u1.x + p2 * u2.x + p3 * u3.x;
        acc.y += p0 * u0.y + p1 * u1.y + p2 * u2.y + p3 * u3.y;
        acc.z += p0 * u0.z + p1 * u1.z + p2 * u2.z + p3 * u3.z;
        acc.w += p0 * u0.w + p1 * u1.w + p2 * u2.w + p3 * u3.w;
        den += p0 + p1 + p2 + p3;
    }
    for (; e < end; ++e) {
        int s0 = __ldg(&g_csr_src[e]);
        float4 u0 = ldh4(&g_xlh[(size_t)s0 * 128 + lane * 4]);
        float p0 = edge_p(u0, r4, a4);
        acc.x += p0 * u0.x; acc.y += p0 * u0.y;
        acc.z += p0 * u0.z; acc.w += p0 * u0.w;
        den += p0;
    }

    float inv = 1.0f / (den + 1e-16f);
    float4 b4 = bias ? *(const float4*)&bias[lane * 4]
                     : make_float4(0.f, 0.f, 0.f, 0.f);
    float4 o;
    o.x = acc.x * inv + b4.x;
    o.y = acc.y * inv + b4.y;
    o.z = acc.z * inv + b4.z;
    o.w = acc.w * inv + b4.w;
    if (doRelu) {
        o.x = o.x > 0.f ? o.x : 0.f;
        o.y = o.y > 0.f ? o.y : 0.f;
        o.z = o.z > 0.f ? o.z : 0.f;
        o.w = o.w > 0.f ? o.w : 0.f;
    }
    *(float4*)&g_h[(size_t)d * 128 + lane * 4] = o;
}

// ================= final fc: out = relu(g_h + b2) @ Wfc + bfc ==============
__global__ void fc_out(const float* __restrict__ Wfc,
                       const float* __restrict__ bfc,
                       const float* __restrict__ b2,
                       float* __restrict__ out, int n) {
    __shared__ float Ws[128 * 10];
    __shared__ float bs[10];
    __shared__ float b2s[128];
    for (int i = threadIdx.x; i < 1280; i += blockDim.x) Ws[i] = Wfc[i];
    if (threadIdx.x < 10)  bs[threadIdx.x]  = bfc[threadIdx.x];
    if (threadIdx.x < 128) b2s[threadIdx.x] = b2[threadIdx.x];
    __syncthreads();
    int idx = blockIdx.x * blockDim.x + threadIdx.x;
    if (idx >= n * 10) return;
    int node = idx / 10;
    int c    = idx % 10;
    const float* hrow = &g_h[(size_t)node * 128];
    float acc = bs[c];
    #pragma unroll
    for (int k = 0; k < 128; ++k) {
        float hv = hrow[k] + b2s[k];
        hv = hv > 0.f ? hv : 0.f;
        acc += hv * Ws[k * 10 + c];
    }
    out[idx] = acc;
}

// ================= launch ==================================================
extern "C" void kernel_launch(void* const* d_in, const int* in_sizes, int n_in,
                              void* d_out, int out_size) {
    const float* x    = (const float*)d_in[0];
    const int*   ei   = (const int*)  d_in[1];
    const float* Wl1  = (const float*)d_in[2];
    const float* Wr1  = (const float*)d_in[3];
    const float* att1 = (const float*)d_in[4];
    const float* b1   = (const float*)d_in[5];
    const float* Wl2  = (const float*)d_in[6];
    const float* Wr2  = (const float*)d_in[7];
    const float* att2 = (const float*)d_in[8];
    const float* b2   = (const float*)d_in[9];
    const float* Wfc  = (const float*)d_in[10];
    const float* bfc  = (const float*)d_in[11];
    float* out = (float*)d_out;

    int n = in_sizes[0] / 128;
    int E = in_sizes[1] / 2;

    int nb_scan    = (n + 1023) / 1024;
    int gat_blocks = (n + 7) / 8;
    int fc_blocks  = (n * 10 + 255) / 256;
    int e_blocks   = (E + 255) / 256;
    int n_blocks   = (n + 255) / 256;

    static int inited = 0;
    static cudaStream_t s_csr;
    static cudaEvent_t  ev_fork, ev_join;
    if (!inited) {
        cudaFuncSetAttribute(dual_gemm_bf16p,
                             cudaFuncAttributeMaxDynamicSharedMemorySize,
                             DG_SMEM_BYTES);
        cudaStreamCreateWithFlags(&s_csr, cudaStreamNonBlocking);
        cudaEventCreateWithFlags(&ev_fork, cudaEventDisableTiming);
        cudaEventCreateWithFlags(&ev_join, cudaEventDisableTiming);
        inited = 1;
    }

    // ---- fork: CSR build (s_csr)  ||  layer-1 GEMM (default) ----
    cudaEventRecord(ev_fork, 0);
    cudaStreamWaitEvent(s_csr, ev_fork, 0);

    deg_zero<<<n_blocks, 256, 0, s_csr>>>(n);
    deg_count<<<e_blocks, 256, 0, s_csr>>>(ei, E);
    scan1<<<nb_scan, 1024, 0, s_csr>>>(n);
    scan3<<<n_blocks, 256, 0, s_csr>>>(n, E, nb_scan);
    scatter<<<e_blocks, 256, 0, s_csr>>>(ei, E);
    cudaEventRecord(ev_join, s_csr);

    dual_gemm_bf16p<<<NSM, 256, DG_SMEM_BYTES>>>(x, Wl1, Wr1, 0, n);

    cudaStreamWaitEvent(0, ev_join, 0);

    // ---- layer 1 ----
    gat_layer<<<gat_blocks, 256>>>(att1, b1, 1, n);

    // ---- layer 2 ----
    dual_gemm_bf16p<<<NSM, 256, DG_SMEM_BYTES>>>(nullptr, Wl2, Wr2, 1, n);
    gat_layer<<<gat_blocks, 256>>>(att2, nullptr, 0, n);

    // ---- fc ----
    fc_out<<<fc_blocks, 256>>>(Wfc, bfc, b2, out, n);
}

// round 9
// speedup vs baseline: 1.8401x; 1.0811x over previous
#include <cuda_runtime.h>
#include <cuda_bf16.h>
#include <cuda_fp16.h>
#include <mma.h>

using namespace nvcuda;

#define MAXN 50000
#define MAXE 800000
#define NSM  148
#define SW   136          // padded smem row stride (bf16 elems)

// ---------------- scratch (device globals; no allocation allowed) ----------
__device__ __half g_xlh[MAXN * 128];   // source transform, fp16 (messages)
__device__ float  g_xr [MAXN * 128];   // target transform, fp32
__device__ float  g_h  [MAXN * 128];   // layer output / next activation
__device__ int    g_deg[MAXN];
__device__ int    g_rowptr[MAXN + 1];
__device__ int    g_blocksum[64];
__device__ int    g_csr_src[MAXE];

// ================= CSR build (by dst) ======================================
__global__ void deg_zero(int n) {
    int i = blockIdx.x * blockDim.x + threadIdx.x;
    if (i < n) g_deg[i] = 0;
}

__global__ void deg_count(const int* __restrict__ ei, int E) {
    int i = blockIdx.x * blockDim.x + threadIdx.x;
    if (i < E) atomicAdd(&g_deg[__ldg(&ei[E + i])], 1);
}

__global__ void scan1(int n) {
    __shared__ int s[1024];
    int i = blockIdx.x * 1024 + threadIdx.x;
    int v = (i < n) ? g_deg[i] : 0;
    s[threadIdx.x] = v;
    __syncthreads();
    #pragma unroll
    for (int off = 1; off < 1024; off <<= 1) {
        int t = (threadIdx.x >= off) ? s[threadIdx.x - off] : 0;
        __syncthreads();
        s[threadIdx.x] += t;
        __syncthreads();
    }
    if (i < n) g_rowptr[i] = s[threadIdx.x] - v;
    if (threadIdx.x == 1023) g_blocksum[blockIdx.x] = s[1023];
}

__global__ void scan3(int n, int E, int nb) {
    __shared__ int bs[64];
    int tid = threadIdx.x;
    if (tid < 64) bs[tid] = (tid < nb) ? g_blocksum[tid] : 0;
    __syncthreads();
    #pragma unroll
    for (int off = 1; off < 64; off <<= 1) {
        int t = (tid < 64 && tid >= off) ? bs[tid - off] : 0;
        __syncthreads();
        if (tid < 64) bs[tid] += t;
        __syncthreads();
    }
    int i = blockIdx.x * blockDim.x + tid;
    if (i < n) {
        int b = i >> 10;
        int pre = (b == 0) ? 0 : bs[b - 1];
        g_rowptr[i] += pre;
        g_deg[i] = 0;
    }
    if (i == 0) g_rowptr[n] = E;
}

__global__ void scatter(const int* __restrict__ ei, int E) {
    int i = blockIdx.x * blockDim.x + threadIdx.x;
    if (i >= E) return;
    int s = __ldg(&ei[i]);
    int d = __ldg(&ei[E + i]);
    int pos = g_rowptr[d] + atomicAdd(&g_deg[d], 1);
    g_csr_src[pos] = s;
}

// ============ persistent dual GEMM, W register-resident (bf16 x3) ==========
// 148 blocks, 256 threads. warp w: matrix m = w>>2 (0:xl->fp16, 1:xr->fp32),
// strips = cols [(w&3)*32, +32) as two 16-col frags. All W frags (2 strips x
// 8 k x hi/lo) live in registers. Chunk = 32 A rows staged hi/lo in smem.
using fA = wmma::fragment<wmma::matrix_a, 16, 16, 16, __nv_bfloat16, wmma::row_major>;
using fB = wmma::fragment<wmma::matrix_b, 16, 16, 16, __nv_bfloat16, wmma::row_major>;
using fC = wmma::fragment<wmma::accumulator, 16, 16, 16, float>;

__device__ __forceinline__ void cvt4(float4 v, __nv_bfloat16* hi, __nv_bfloat16* lo) {
    __nv_bfloat16 h0 = __float2bfloat16(v.x);
    __nv_bfloat16 h1 = __float2bfloat16(v.y);
    __nv_bfloat16 h2 = __float2bfloat16(v.z);
    __nv_bfloat16 h3 = __float2bfloat16(v.w);
    hi[0] = h0; hi[1] = h1; hi[2] = h2; hi[3] = h3;
    lo[0] = __float2bfloat16(v.x - __bfloat162float(h0));
    lo[1] = __float2bfloat16(v.y - __bfloat162float(h1));
    lo[2] = __float2bfloat16(v.z - __bfloat162float(h2));
    lo[3] = __float2bfloat16(v.w - __bfloat162float(h3));
}

__global__ void __launch_bounds__(256, 1)
dual_gemm_wreg(const float* __restrict__ Aext,
               const float* __restrict__ Wl,
               const float* __restrict__ Wr,
               int useH, int n) {
    // union region: W staging (128 x SW bf16 = 34816B)
    //               A hi/lo   (2 x 32 x SW bf16 = 17408B) at offset 0
    //               xl fp32 staging (32x128 = 16384B)     at offset 17408
    __shared__ __align__(16) unsigned char smem_u[34816];
    __nv_bfloat16* ws   = (__nv_bfloat16*)smem_u;          // W stage
    __nv_bfloat16* ah_s = (__nv_bfloat16*)smem_u;          // A hi
    __nv_bfloat16* al_s = ah_s + 32 * SW;                  // A lo
    float*         stg  = (float*)(smem_u + 17408);        // xl fp32 stage

    const float* A = useH ? g_h : Aext;
    const float* Wmat[2] = {Wl, Wr};
    int tid   = threadIdx.x;
    int warp  = tid >> 5;
    int mat   = warp >> 2;          // 0 = xl, 1 = xr
    int sbase = (warp & 3) * 32;    // first col of this warp's 32-col span

    // ---- load W fragments into registers (4 staging passes) ----
    fB wf[2][2][8];                 // [strip][part][k]
    #pragma unroll
    for (int m = 0; m < 2; ++m) {
        #pragma unroll
        for (int part = 0; part < 2; ++part) {
            __syncthreads();        // previous consumers done with region
            #pragma unroll
            for (int t = 0; t < 16; ++t) {
                int f  = tid + t * 256;        // 0..4095 float4
                int r  = f >> 5;               // 0..127
                int c4 = (f & 31) * 4;
                float4 v = *(const float4*)&Wmat[m][(size_t)r * 128 + c4];
                __nv_bfloat16 b0 = __float2bfloat16(v.x);
                __nv_bfloat16 b1 = __float2bfloat16(v.y);
                __nv_bfloat16 b2 = __float2bfloat16(v.z);
                __nv_bfloat16 b3 = __float2bfloat16(v.w);
                __nv_bfloat16* dst = &ws[r * SW + c4];
                if (part == 0) {
                    dst[0] = b0; dst[1] = b1; dst[2] = b2; dst[3] = b3;
                } else {
                    dst[0] = __float2bfloat16(v.x - __bfloat162float(b0));
                    dst[1] = __float2bfloat16(v.y - __bfloat162float(b1));
                    dst[2] = __float2bfloat16(v.z - __bfloat162float(b2));
                    dst[3] = __float2bfloat16(v.w - __bfloat162float(b3));
                }
            }
            __syncthreads();
            if (mat == m) {
                #pragma unroll
                for (int k = 0; k < 8; ++k) {
                    #pragma unroll
                    for (int s = 0; s < 2; ++s)
                        wmma::load_matrix_sync(wf[s][part][k],
                                               &ws[k * 16 * SW + sbase + s * 16], SW);
                }
            }
        }
    }
    __syncthreads();                 // region free for A staging

    int nchunks = (n + 31) >> 5;
    for (int c = blockIdx.x; c < nchunks; c += gridDim.x) {
        int row0 = c * 32;
        // ---- stage A chunk 32x128 -> bf16 hi/lo (1024 f4, 4/thread) ----
        #pragma unroll
        for (int t = 0; t < 4; ++t) {
            int f  = tid + t * 256;
            int r  = f >> 5;
            int c4 = (f & 31) * 4;
            float4 v = make_float4(0.f, 0.f, 0.f, 0.f);
            if (row0 + r < n)
                v = *(const float4*)&A[(size_t)(row0 + r) * 128 + c4];
            cvt4(v, &ah_s[r * SW + c4], &al_s[r * SW + c4]);
        }
        __syncthreads();

        fC acc[2][2];                // [rt][strip]
        #pragma unroll
        for (int i = 0; i < 2; ++i)
            #pragma unroll
            for (int j = 0; j < 2; ++j)
                wmma::fill_fragment(acc[i][j], 0.0f);

        #pragma unroll
        for (int k = 0; k < 8; ++k) {
            fA ah[2], al[2];
            #pragma unroll
            for (int rt = 0; rt < 2; ++rt) {
                wmma::load_matrix_sync(ah[rt], &ah_s[rt * 16 * SW + k * 16], SW);
                wmma::load_matrix_sync(al[rt], &al_s[rt * 16 * SW + k * 16], SW);
            }
            // 3 terms, 4 independent accs between same-acc reuse
            #pragma unroll
            for (int rt = 0; rt < 2; ++rt)
                #pragma unroll
                for (int s = 0; s < 2; ++s)
                    wmma::mma_sync(acc[rt][s], ah[rt], wf[s][0][k], acc[rt][s]);
            #pragma unroll
            for (int rt = 0; rt < 2; ++rt)
                #pragma unroll
                for (int s = 0; s < 2; ++s)
                    wmma::mma_sync(acc[rt][s], ah[rt], wf[s][1][k], acc[rt][s]);
            #pragma unroll
            for (int rt = 0; rt < 2; ++rt)
                #pragma unroll
                for (int s = 0; s < 2; ++s)
                    wmma::mma_sync(acc[rt][s], al[rt], wf[s][0][k], acc[rt][s]);
        }
        __syncthreads();             // A consumed; stg region usable

        if (mat == 1) {
            // xr: direct fp32 store
            #pragma unroll
            for (int rt = 0; rt < 2; ++rt) {
                int wrow0 = row0 + rt * 16;
                if (wrow0 < n) {
                    #pragma unroll
                    for (int s = 0; s < 2; ++s)
                        wmma::store_matrix_sync(
                            &g_xr[(size_t)wrow0 * 128 + sbase + s * 16],
                            acc[rt][s], 128, wmma::mem_row_major);
                }
            }
        } else {
            // xl: stage fp32 into smem for fp16 conversion
            #pragma unroll
            for (int rt = 0; rt < 2; ++rt) {
                #pragma unroll
                for (int s = 0; s < 2; ++s)
                    wmma::store_matrix_sync(
                        &stg[(size_t)(rt * 16) * 128 + sbase + s * 16],
                        acc[rt][s], 128, wmma::mem_row_major);
            }
        }
        __syncthreads();

        // cooperative fp32->fp16 conversion of xl (32x128 = 1024 f4)
        #pragma unroll
        for (int t = 0; t < 4; ++t) {
            int f  = tid + t * 256;
            int r  = f >> 5;
            int c4 = (f & 31) * 4;
            if (row0 + r < n) {
                float4 v = *(const float4*)&stg[r * 128 + c4];
                __half2 a = __floats2half2_rn(v.x, v.y);
                __half2 b = __floats2half2_rn(v.z, v.w);
                uint2 u;
                u.x = *(unsigned*)&a;
                u.y = *(unsigned*)&b;
                *(uint2*)&g_xlh[(size_t)(row0 + r) * 128 + c4] = u;
            }
        }
        __syncthreads();             // stg/A region free for next chunk
    }
}

// ================= fused GAT layer: warp per dst node ======================
__device__ __forceinline__ float4 ldh4(const __half* p) {
    uint2 u = *(const uint2*)p;
    __half2 h0 = *reinterpret_cast<__half2*>(&u.x);
    __half2 h1 = *reinterpret_cast<__half2*>(&u.y);
    float2 f0 = __half22float2(h0);
    float2 f1 = __half22float2(h1);
    return make_float4(f0.x, f0.y, f1.x, f1.y);
}

__device__ __forceinline__ float edge_p(float4 l4, float4 r4, float4 a4) {
    float v0 = l4.x + r4.x; v0 = v0 > 0.f ? v0 : 0.2f * v0;
    float v1 = l4.y + r4.y; v1 = v1 > 0.f ? v1 : 0.2f * v1;
    float v2 = l4.z + r4.z; v2 = v2 > 0.f ? v2 : 0.2f * v2;
    float v3 = l4.w + r4.w; v3 = v3 > 0.f ? v3 : 0.2f * v3;
    float part = v0 * a4.x + v1 * a4.y + v2 * a4.z + v3 * a4.w;
    part += __shfl_xor_sync(0xffffffffu, part, 1);
    part += __shfl_xor_sync(0xffffffffu, part, 2);
    return __expf(part);
}

__global__ void gat_layer(const float* __restrict__ att,
                          const float* __restrict__ bias,
                          int doRelu, int n) {
    int d = blockIdx.x * 8 + (threadIdx.x >> 5);
    if (d >= n) return;
    int lane = threadIdx.x & 31;

    float4 a4 = *(const float4*)&att[lane * 4];
    float4 r4 = *(const float4*)&g_xr[(size_t)d * 128 + lane * 4];

    float4 l4 = ldh4(&g_xlh[(size_t)d * 128 + lane * 4]);
    float p = edge_p(l4, r4, a4);
    float4 acc = make_float4(p * l4.x, p * l4.y, p * l4.z, p * l4.w);
    float den = p;

    int e   = g_rowptr[d];
    int end = g_rowptr[d + 1];

    for (; e + 3 < end; e += 4) {
        int s0 = __ldg(&g_csr_src[e]);
        int s1 = __ldg(&g_csr_src[e + 1]);
        int s2 = __ldg(&g_csr_src[e + 2]);
        int s3 = __ldg(&g_csr_src[e + 3]);
        float4 u0 = ldh4(&g_xlh[(size_t)s0 * 128 + lane * 4]);
        float4 u1 = ldh4(&g_xlh[(size_t)s1 * 128 + lane * 4]);
        float4 u2 = ldh4(&g_xlh[(size_t)s2 * 128 + lane * 4]);
        float4 u3 = ldh4(&g_xlh[(size_t)s3 * 128 + lane * 4]);
        float p0 = edge_p(u0, r4, a4);
        float p1 = edge_p(u1, r4, a4);
        float p2 = edge_p(u2, r4, a4);
        float p3 = edge_p(u3, r4, a4);
        acc.x += p0 * u0.x + p1 * u1.x + p2 * u2.x + p3 * u3.x;
        acc.y += p0 * u0.y + p1 * u1.y + p2 * u2.y + p3 * u3.y;
        acc.z += p0 * u0.z + p1 * u1.z + p2 * u2.z + p3 * u3.z;
        acc.w += p0 * u0.w + p1 * u1.w + p2 * u2.w + p3 * u3.w;
        den += p0 + p1 + p2 + p3;
    }
    for (; e < end; ++e) {
        int s0 = __ldg(&g_csr_src[e]);
        float4 u0 = ldh4(&g_xlh[(size_t)s0 * 128 + lane * 4]);
        float p0 = edge_p(u0, r4, a4);
        acc.x += p0 * u0.x; acc.y += p0 * u0.y;
        acc.z += p0 * u0.z; acc.w += p0 * u0.w;
        den += p0;
    }

    float inv = 1.0f / (den + 1e-16f);
    float4 b4 = bias ? *(const float4*)&bias[lane * 4]
                     : make_float4(0.f, 0.f, 0.f, 0.f);
    float4 o;
    o.x = acc.x * inv + b4.x;
    o.y = acc.y * inv + b4.y;
    o.z = acc.z * inv + b4.z;
    o.w = acc.w * inv + b4.w;
    if (doRelu) {
        o.x = o.x > 0.f ? o.x : 0.f;
        o.y = o.y > 0.f ? o.y : 0.f;
        o.z = o.z > 0.f ? o.z : 0.f;
        o.w = o.w > 0.f ? o.w : 0.f;
    }
    *(float4*)&g_h[(size_t)d * 128 + lane * 4] = o;
}

// ================= final fc: out = relu(g_h + b2) @ Wfc + bfc ==============
__global__ void fc_out(const float* __restrict__ Wfc,
                       const float* __restrict__ bfc,
                       const float* __restrict__ b2,
                       float* __restrict__ out, int n) {
    __shared__ float Ws[128 * 10];
    __shared__ float bs[10];
    __shared__ float b2s[128];
    for (int i = threadIdx.x; i < 1280; i += blockDim.x) Ws[i] = Wfc[i];
    if (threadIdx.x < 10)  bs[threadIdx.x]  = bfc[threadIdx.x];
    if (threadIdx.x < 128) b2s[threadIdx.x] = b2[threadIdx.x];
    __syncthreads();
    int idx = blockIdx.x * blockDim.x + threadIdx.x;
    if (idx >= n * 10) return;
    int node = idx / 10;
    int c    = idx % 10;
    const float* hrow = &g_h[(size_t)node * 128];
    float acc = bs[c];
    #pragma unroll
    for (int k = 0; k < 128; ++k) {
        float hv = hrow[k] + b2s[k];
        hv = hv > 0.f ? hv : 0.f;
        acc += hv * Ws[k * 10 + c];
    }
    out[idx] = acc;
}

// ================= launch ==================================================
extern "C" void kernel_launch(void* const* d_in, const int* in_sizes, int n_in,
                              void* d_out, int out_size) {
    const float* x    = (const float*)d_in[0];
    const int*   ei   = (const int*)  d_in[1];
    const float* Wl1  = (const float*)d_in[2];
    const float* Wr1  = (const float*)d_in[3];
    const float* att1 = (const float*)d_in[4];
    const float* b1   = (const float*)d_in[5];
    const float* Wl2  = (const float*)d_in[6];
    const float* Wr2  = (const float*)d_in[7];
    const float* att2 = (const float*)d_in[8];
    const float* b2   = (const float*)d_in[9];
    const float* Wfc  = (const float*)d_in[10];
    const float* bfc  = (const float*)d_in[11];
    float* out = (float*)d_out;

    int n = in_sizes[0] / 128;
    int E = in_sizes[1] / 2;

    int nb_scan    = (n + 1023) / 1024;
    int gat_blocks = (n + 7) / 8;
    int fc_blocks  = (n * 10 + 255) / 256;
    int e_blocks   = (E + 255) / 256;
    int n_blocks   = (n + 255) / 256;

    static int inited = 0;
    static cudaStream_t s_csr;
    static cudaEvent_t  ev_fork, ev_join;
    if (!inited) {
        cudaStreamCreateWithFlags(&s_csr, cudaStreamNonBlocking);
        cudaEventCreateWithFlags(&ev_fork, cudaEventDisableTiming);
        cudaEventCreateWithFlags(&ev_join, cudaEventDisableTiming);
        inited = 1;
    }

    // ---- fork: CSR build (s_csr)  ||  layer-1 GEMM (default) ----
    // (dual_gemm submitted 4th so the ncu -s5-c1 slot profiles it)
    cudaEventRecord(ev_fork, 0);
    cudaStreamWaitEvent(s_csr, ev_fork, 0);

    deg_zero<<<n_blocks, 256, 0, s_csr>>>(n);
    deg_count<<<e_blocks, 256, 0, s_csr>>>(ei, E);
    scan1<<<nb_scan, 1024, 0, s_csr>>>(n);

    dual_gemm_wreg<<<NSM, 256>>>(x, Wl1, Wr1, 0, n);   // 4th submission

    scan3<<<n_blocks, 256, 0, s_csr>>>(n, E, nb_scan);
    scatter<<<e_blocks, 256, 0, s_csr>>>(ei, E);
    cudaEventRecord(ev_join, s_csr);

    cudaStreamWaitEvent(0, ev_join, 0);

    // ---- layer 1 ----
    gat_layer<<<gat_blocks, 256>>>(att1, b1, 1, n);

    // ---- layer 2 ----
    dual_gemm_wreg<<<NSM, 256>>>(nullptr, Wl2, Wr2, 1, n);
    gat_layer<<<gat_blocks, 256>>>(att2, nullptr, 0, n);

    // ---- fc ----
    fc_out<<<fc_blocks, 256>>>(Wfc, bfc, b2, out, n);
}

// round 10
// speedup vs baseline: 1.8452x; 1.0028x over previous
#include <cuda_runtime.h>
#include <cuda_bf16.h>
#include <cuda_fp16.h>
#include <mma.h>

using namespace nvcuda;

#define MAXN 50000
#define MAXE 800000
#define NSM  148
#define SW   136          // padded smem row stride (bf16 elems)

// ---------------- scratch (device globals; no allocation allowed) ----------
__device__ __half g_xlh[MAXN * 128];   // source transform, fp16 (messages)
__device__ float  g_xr [MAXN * 128];   // target transform, fp32
__device__ float  g_h  [MAXN * 128];   // layer output / next activation
__device__ int    g_deg[MAXN];
__device__ int    g_rowptr[MAXN + 1];
__device__ int    g_blocksum[64];
__device__ int    g_csr_src[MAXE];

// ================= CSR build (by dst) ======================================
__global__ void deg_zero(int n) {
    int i = blockIdx.x * blockDim.x + threadIdx.x;
    if (i < n) g_deg[i] = 0;
}

__global__ void deg_count(const int* __restrict__ ei, int E) {
    int i = blockIdx.x * blockDim.x + threadIdx.x;
    if (i < E) atomicAdd(&g_deg[__ldg(&ei[E + i])], 1);
}

__global__ void scan1(int n) {
    __shared__ int s[1024];
    int i = blockIdx.x * 1024 + threadIdx.x;
    int v = (i < n) ? g_deg[i] : 0;
    s[threadIdx.x] = v;
    __syncthreads();
    #pragma unroll
    for (int off = 1; off < 1024; off <<= 1) {
        int t = (threadIdx.x >= off) ? s[threadIdx.x - off] : 0;
        __syncthreads();
        s[threadIdx.x] += t;
        __syncthreads();
    }
    if (i < n) g_rowptr[i] = s[threadIdx.x] - v;
    if (threadIdx.x == 1023) g_blocksum[blockIdx.x] = s[1023];
}

__global__ void scan3(int n, int E, int nb) {
    __shared__ int bs[64];
    int tid = threadIdx.x;
    if (tid < 64) bs[tid] = (tid < nb) ? g_blocksum[tid] : 0;
    __syncthreads();
    #pragma unroll
    for (int off = 1; off < 64; off <<= 1) {
        int t = (tid < 64 && tid >= off) ? bs[tid - off] : 0;
        __syncthreads();
        if (tid < 64) bs[tid] += t;
        __syncthreads();
    }
    int i = blockIdx.x * blockDim.x + tid;
    if (i < n) {
        int b = i >> 10;
        int pre = (b == 0) ? 0 : bs[b - 1];
        g_rowptr[i] += pre;
        g_deg[i] = 0;
    }
    if (i == 0) g_rowptr[n] = E;
}

__global__ void scatter(const int* __restrict__ ei, int E) {
    int i = blockIdx.x * blockDim.x + threadIdx.x;
    if (i >= E) return;
    int s = __ldg(&ei[i]);
    int d = __ldg(&ei[E + i]);
    int pos = g_rowptr[d] + atomicAdd(&g_deg[d], 1);
    g_csr_src[pos] = s;
}

// ============ persistent dual GEMM, W register-resident (bf16 x3) ==========
// 148 blocks x 512 threads (16 warps). warp w: matrix m = w>>3
// (0: xl->fp16, 1: xr->fp32), strip = cols [(w&7)*16, +16).
// Per warp: 16 W frags (hi/lo x 8k) in regs, 2 accumulators (32-row chunk).
using fA = wmma::fragment<wmma::matrix_a, 16, 16, 16, __nv_bfloat16, wmma::row_major>;
using fB = wmma::fragment<wmma::matrix_b, 16, 16, 16, __nv_bfloat16, wmma::row_major>;
using fC = wmma::fragment<wmma::accumulator, 16, 16, 16, float>;

__device__ __forceinline__ void cvt4(float4 v, __nv_bfloat16* hi, __nv_bfloat16* lo) {
    __nv_bfloat16 h0 = __float2bfloat16(v.x);
    __nv_bfloat16 h1 = __float2bfloat16(v.y);
    __nv_bfloat16 h2 = __float2bfloat16(v.z);
    __nv_bfloat16 h3 = __float2bfloat16(v.w);
    hi[0] = h0; hi[1] = h1; hi[2] = h2; hi[3] = h3;
    lo[0] = __float2bfloat16(v.x - __bfloat162float(h0));
    lo[1] = __float2bfloat16(v.y - __bfloat162float(h1));
    lo[2] = __float2bfloat16(v.z - __bfloat162float(h2));
    lo[3] = __float2bfloat16(v.w - __bfloat162float(h3));
}

__global__ void __launch_bounds__(512, 1)
dual_gemm_wreg(const float* __restrict__ Aext,
               const float* __restrict__ Wl,
               const float* __restrict__ Wr,
               int useH, int n) {
    // union region (34816B): W staging 128xSW bf16
    //                        A hi/lo 2x32xSW bf16 (17408B) at 0
    //                        xl fp32 staging 32x128 (16384B) at 17408
    __shared__ __align__(16) unsigned char smem_u[34816];
    __nv_bfloat16* ws   = (__nv_bfloat16*)smem_u;
    __nv_bfloat16* ah_s = (__nv_bfloat16*)smem_u;
    __nv_bfloat16* al_s = ah_s + 32 * SW;
    float*         stg  = (float*)(smem_u + 17408);

    const float* A = useH ? g_h : Aext;
    const float* Wmat[2] = {Wl, Wr};
    int tid   = threadIdx.x;
    int warp  = tid >> 5;
    int mat   = warp >> 3;          // 0 = xl, 1 = xr
    int sbase = (warp & 7) * 16;    // this warp's 16-col strip

    // ---- load W fragments into registers (4 staging passes) ----
    fB wf[2][8];                    // [part][k]
    #pragma unroll
    for (int m = 0; m < 2; ++m) {
        #pragma unroll
        for (int part = 0; part < 2; ++part) {
            __syncthreads();
            #pragma unroll
            for (int t = 0; t < 8; ++t) {
                int f  = tid + t * 512;        // 0..4095 float4
                int r  = f >> 5;
                int c4 = (f & 31) * 4;
                float4 v = *(const float4*)&Wmat[m][(size_t)r * 128 + c4];
                __nv_bfloat16 b0 = __float2bfloat16(v.x);
                __nv_bfloat16 b1 = __float2bfloat16(v.y);
                __nv_bfloat16 b2 = __float2bfloat16(v.z);
                __nv_bfloat16 b3 = __float2bfloat16(v.w);
                __nv_bfloat16* dst = &ws[r * SW + c4];
                if (part == 0) {
                    dst[0] = b0; dst[1] = b1; dst[2] = b2; dst[3] = b3;
                } else {
                    dst[0] = __float2bfloat16(v.x - __bfloat162float(b0));
                    dst[1] = __float2bfloat16(v.y - __bfloat162float(b1));
                    dst[2] = __float2bfloat16(v.z - __bfloat162float(b2));
                    dst[3] = __float2bfloat16(v.w - __bfloat162float(b3));
                }
            }
            __syncthreads();
            if (mat == m) {
                #pragma unroll
                for (int k = 0; k < 8; ++k)
                    wmma::load_matrix_sync(wf[part][k],
                                           &ws[k * 16 * SW + sbase], SW);
            }
        }
    }
    __syncthreads();

    int nchunks = (n + 31) >> 5;
    for (int c = blockIdx.x; c < nchunks; c += gridDim.x) {
        int row0 = c * 32;
        // ---- stage A chunk 32x128 -> bf16 hi/lo (1024 f4, 2/thread) ----
        #pragma unroll
        for (int t = 0; t < 2; ++t) {
            int f  = tid + t * 512;
            int r  = f >> 5;
            int c4 = (f & 31) * 4;
            float4 v = make_float4(0.f, 0.f, 0.f, 0.f);
            if (row0 + r < n)
                v = *(const float4*)&A[(size_t)(row0 + r) * 128 + c4];
            cvt4(v, &ah_s[r * SW + c4], &al_s[r * SW + c4]);
        }
        __syncthreads();

        fC acc[2];                   // row tiles 0,1
        wmma::fill_fragment(acc[0], 0.0f);
        wmma::fill_fragment(acc[1], 0.0f);

        #pragma unroll
        for (int k = 0; k < 8; ++k) {
            fA ah[2], al[2];
            wmma::load_matrix_sync(ah[0], &ah_s[0 * SW + k * 16], SW);
            wmma::load_matrix_sync(ah[1], &ah_s[16 * SW + k * 16], SW);
            wmma::load_matrix_sync(al[0], &al_s[0 * SW + k * 16], SW);
            wmma::load_matrix_sync(al[1], &al_s[16 * SW + k * 16], SW);
            // interleave the two independent acc chains
            wmma::mma_sync(acc[0], ah[0], wf[0][k], acc[0]);
            wmma::mma_sync(acc[1], ah[1], wf[0][k], acc[1]);
            wmma::mma_sync(acc[0], ah[0], wf[1][k], acc[0]);
            wmma::mma_sync(acc[1], ah[1], wf[1][k], acc[1]);
            wmma::mma_sync(acc[0], al[0], wf[0][k], acc[0]);
            wmma::mma_sync(acc[1], al[1], wf[0][k], acc[1]);
        }
        __syncthreads();             // A consumed; stg region usable

        if (mat == 1) {
            #pragma unroll
            for (int rt = 0; rt < 2; ++rt) {
                int wrow0 = row0 + rt * 16;
                if (wrow0 < n)
                    wmma::store_matrix_sync(
                        &g_xr[(size_t)wrow0 * 128 + sbase],
                        acc[rt], 128, wmma::mem_row_major);
            }
        } else {
            #pragma unroll
            for (int rt = 0; rt < 2; ++rt)
                wmma::store_matrix_sync(
                    &stg[(size_t)(rt * 16) * 128 + sbase],
                    acc[rt], 128, wmma::mem_row_major);
        }
        __syncthreads();

        // cooperative fp32->fp16 conversion of xl (1024 f4, 2/thread)
        #pragma unroll
        for (int t = 0; t < 2; ++t) {
            int f  = tid + t * 512;
            int r  = f >> 5;
            int c4 = (f & 31) * 4;
            if (row0 + r < n) {
                float4 v = *(const float4*)&stg[r * 128 + c4];
                __half2 a = __floats2half2_rn(v.x, v.y);
                __half2 b = __floats2half2_rn(v.z, v.w);
                uint2 u;
                u.x = *(unsigned*)&a;
                u.y = *(unsigned*)&b;
                *(uint2*)&g_xlh[(size_t)(row0 + r) * 128 + c4] = u;
            }
        }
        __syncthreads();
    }
}

// ================= fused GAT layer: warp per dst node ======================
__device__ __forceinline__ float4 ldh4(const __half* p) {
    uint2 u = *(const uint2*)p;
    __half2 h0 = *reinterpret_cast<__half2*>(&u.x);
    __half2 h1 = *reinterpret_cast<__half2*>(&u.y);
    float2 f0 = __half22float2(h0);
    float2 f1 = __half22float2(h1);
    return make_float4(f0.x, f0.y, f1.x, f1.y);
}

__device__ __forceinline__ float edge_p(float4 l4, float4 r4, float4 a4) {
    float v0 = l4.x + r4.x; v0 = v0 > 0.f ? v0 : 0.2f * v0;
    float v1 = l4.y + r4.y; v1 = v1 > 0.f ? v1 : 0.2f * v1;
    float v2 = l4.z + r4.z; v2 = v2 > 0.f ? v2 : 0.2f * v2;
    float v3 = l4.w + r4.w; v3 = v3 > 0.f ? v3 : 0.2f * v3;
    float part = v0 * a4.x + v1 * a4.y + v2 * a4.z + v3 * a4.w;
    part += __shfl_xor_sync(0xffffffffu, part, 1);
    part += __shfl_xor_sync(0xffffffffu, part, 2);
    return __expf(part);
}

__global__ void gat_layer(const float* __restrict__ att,
                          const float* __restrict__ bias,
                          int doRelu, int n) {
    int d = blockIdx.x * 8 + (threadIdx.x >> 5);
    if (d >= n) return;
    int lane = threadIdx.x & 31;

    float4 a4 = *(const float4*)&att[lane * 4];
    float4 r4 = *(const float4*)&g_xr[(size_t)d * 128 + lane * 4];

    float4 l4 = ldh4(&g_xlh[(size_t)d * 128 + lane * 4]);
    float p = edge_p(l4, r4, a4);
    float4 acc = make_float4(p * l4.x, p * l4.y, p * l4.z, p * l4.w);
    float den = p;

    int e   = g_rowptr[d];
    int end = g_rowptr[d + 1];

    for (; e + 3 < end; e += 4) {
        int s0 = __ldg(&g_csr_src[e]);
        int s1 = __ldg(&g_csr_src[e + 1]);
        int s2 = __ldg(&g_csr_src[e + 2]);
        int s3 = __ldg(&g_csr_src[e + 3]);
        float4 u0 = ldh4(&g_xlh[(size_t)s0 * 128 + lane * 4]);
        float4 u1 = ldh4(&g_xlh[(size_t)s1 * 128 + lane * 4]);
        float4 u2 = ldh4(&g_xlh[(size_t)s2 * 128 + lane * 4]);
        float4 u3 = ldh4(&g_xlh[(size_t)s3 * 128 + lane * 4]);
        float p0 = edge_p(u0, r4, a4);
        float p1 = edge_p(u1, r4, a4);
        float p2 = edge_p(u2, r4, a4);
        float p3 = edge_p(u3, r4, a4);
        acc.x += p0 * u0.x + p1 * u1.x + p2 * u2.x + p3 * u3.x;
        acc.y += p0 * u0.y + p1 * u1.y + p2 * u2.y + p3 * u3.y;
        acc.z += p0 * u0.z + p1 * u1.z + p2 * u2.z + p3 * u3.z;
        acc.w += p0 * u0.w + p1 * u1.w + p2 * u2.w + p3 * u3.w;
        den += p0 + p1 + p2 + p3;
    }
    for (; e < end; ++e) {
        int s0 = __ldg(&g_csr_src[e]);
        float4 u0 = ldh4(&g_xlh[(size_t)s0 * 128 + lane * 4]);
        float p0 = edge_p(u0, r4, a4);
        acc.x += p0 * u0.x; acc.y += p0 * u0.y;
        acc.z += p0 * u0.z; acc.w += p0 * u0.w;
        den += p0;
    }

    float inv = 1.0f / (den + 1e-16f);
    float4 b4 = bias ? *(const float4*)&bias[lane * 4]
                     : make_float4(0.f, 0.f, 0.f, 0.f);
    float4 o;
    o.x = acc.x * inv + b4.x;
    o.y = acc.y * inv + b4.y;
    o.z = acc.z * inv + b4.z;
    o.w = acc.w * inv + b4.w;
    if (doRelu) {
        o.x = o.x > 0.f ? o.x : 0.f;
        o.y = o.y > 0.f ? o.y : 0.f;
        o.z = o.z > 0.f ? o.z : 0.f;
        o.w = o.w > 0.f ? o.w : 0.f;
    }
    *(float4*)&g_h[(size_t)d * 128 + lane * 4] = o;
}

// ================= final fc: out = relu(g_h + b2) @ Wfc + bfc ==============
__global__ void fc_out(const float* __restrict__ Wfc,
                       const float* __restrict__ bfc,
                       const float* __restrict__ b2,
                       float* __restrict__ out, int n) {
    __shared__ float Ws[128 * 10];
    __shared__ float bs[10];
    __shared__ float b2s[128];
    for (int i = threadIdx.x; i < 1280; i += blockDim.x) Ws[i] = Wfc[i];
    if (threadIdx.x < 10)  bs[threadIdx.x]  = bfc[threadIdx.x];
    if (threadIdx.x < 128) b2s[threadIdx.x] = b2[threadIdx.x];
    __syncthreads();
    int idx = blockIdx.x * blockDim.x + threadIdx.x;
    if (idx >= n * 10) return;
    int node = idx / 10;
    int c    = idx % 10;
    const float* hrow = &g_h[(size_t)node * 128];
    float acc = bs[c];
    #pragma unroll
    for (int k = 0; k < 128; ++k) {
        float hv = hrow[k] + b2s[k];
        hv = hv > 0.f ? hv : 0.f;
        acc += hv * Ws[k * 10 + c];
    }
    out[idx] = acc;
}

// ================= launch ==================================================
extern "C" void kernel_launch(void* const* d_in, const int* in_sizes, int n_in,
                              void* d_out, int out_size) {
    const float* x    = (const float*)d_in[0];
    const int*   ei   = (const int*)  d_in[1];
    const float* Wl1  = (const float*)d_in[2];
    const float* Wr1  = (const float*)d_in[3];
    const float* att1 = (const float*)d_in[4];
    const float* b1   = (const float*)d_in[5];
    const float* Wl2  = (const float*)d_in[6];
    const float* Wr2  = (const float*)d_in[7];
    const float* att2 = (const float*)d_in[8];
    const float* b2   = (const float*)d_in[9];
    const float* Wfc  = (const float*)d_in[10];
    const float* bfc  = (const float*)d_in[11];
    float* out = (float*)d_out;

    int n = in_sizes[0] / 128;
    int E = in_sizes[1] / 2;

    int nb_scan    = (n + 1023) / 1024;
    int gat_blocks = (n + 7) / 8;
    int fc_blocks  = (n * 10 + 255) / 256;
    int e_blocks   = (E + 255) / 256;
    int n_blocks   = (n + 255) / 256;

    static int inited = 0;
    static cudaStream_t s_csr;
    static cudaEvent_t  ev_fork, ev_join;
    if (!inited) {
        cudaStreamCreateWithFlags(&s_csr, cudaStreamNonBlocking);
        cudaEventCreateWithFlags(&ev_fork, cudaEventDisableTiming);
        cudaEventCreateWithFlags(&ev_join, cudaEventDisableTiming);
        inited = 1;
    }

    // ---- fork: CSR build (s_csr)  ||  layer-1 GEMM (default) ----
    // (dual_gemm submitted 4th so the ncu slot profiles it)
    cudaEventRecord(ev_fork, 0);
    cudaStreamWaitEvent(s_csr, ev_fork, 0);

    deg_zero<<<n_blocks, 256, 0, s_csr>>>(n);
    deg_count<<<e_blocks, 256, 0, s_csr>>>(ei, E);
    scan1<<<nb_scan, 1024, 0, s_csr>>>(n);

    dual_gemm_wreg<<<NSM, 512>>>(x, Wl1, Wr1, 0, n);   // 4th submission

    scan3<<<n_blocks, 256, 0, s_csr>>>(n, E, nb_scan);
    scatter<<<e_blocks, 256, 0, s_csr>>>(ei, E);
    cudaEventRecord(ev_join, s_csr);

    cudaStreamWaitEvent(0, ev_join, 0);

    // ---- layer 1 ----
    gat_layer<<<gat_blocks, 256>>>(att1, b1, 1, n);

    // ---- layer 2 ----
    dual_gemm_wreg<<<NSM, 512>>>(nullptr, Wl2, Wr2, 1, n);
    gat_layer<<<gat_blocks, 256>>>(att2, nullptr, 0, n);

    // ---- fc ----
    fc_out<<<fc_blocks, 256>>>(Wfc, bfc, b2, out, n);
}

// round 11
// speedup vs baseline: 1.9523x; 1.0580x over previous
#include <cuda_runtime.h>
#include <cuda_bf16.h>
#include <mma.h>

using namespace nvcuda;

#define MAXN 50000
#define MAXE 800000
#define NSM  148
#define SW   136          // padded smem row stride (bf16 elems)

// ---------------- scratch (device globals; no allocation allowed) ----------
__device__ float g_xl[MAXN * 128];
__device__ float g_xr[MAXN * 128];
__device__ float g_h [MAXN * 128];
__device__ int   g_deg[MAXN];
__device__ int   g_rowptr[MAXN + 1];
__device__ int   g_blocksum[64];
__device__ int   g_csr_src[MAXE];

// ================= CSR build (by dst) ======================================
__global__ void deg_zero(int n) {
    int i = blockIdx.x * blockDim.x + threadIdx.x;
    if (i < n) g_deg[i] = 0;
}

__global__ void deg_count(const int* __restrict__ ei, int E) {
    int i = blockIdx.x * blockDim.x + threadIdx.x;
    if (i < E) atomicAdd(&g_deg[__ldg(&ei[E + i])], 1);
}

__global__ void scan1(int n) {
    __shared__ int s[1024];
    int i = blockIdx.x * 1024 + threadIdx.x;
    int v = (i < n) ? g_deg[i] : 0;
    s[threadIdx.x] = v;
    __syncthreads();
    #pragma unroll
    for (int off = 1; off < 1024; off <<= 1) {
        int t = (threadIdx.x >= off) ? s[threadIdx.x - off] : 0;
        __syncthreads();
        s[threadIdx.x] += t;
        __syncthreads();
    }
    if (i < n) g_rowptr[i] = s[threadIdx.x] - v;
    if (threadIdx.x == 1023) g_blocksum[blockIdx.x] = s[1023];
}

__global__ void scan3(int n, int E, int nb) {
    __shared__ int bs[64];
    int tid = threadIdx.x;
    if (tid < 64) bs[tid] = (tid < nb) ? g_blocksum[tid] : 0;
    __syncthreads();
    #pragma unroll
    for (int off = 1; off < 64; off <<= 1) {
        int t = (tid < 64 && tid >= off) ? bs[tid - off] : 0;
        __syncthreads();
        if (tid < 64) bs[tid] += t;
        __syncthreads();
    }
    int i = blockIdx.x * blockDim.x + tid;
    if (i < n) {
        int b = i >> 10;
        int pre = (b == 0) ? 0 : bs[b - 1];
        g_rowptr[i] += pre;
        g_deg[i] = 0;
    }
    if (i == 0) g_rowptr[n] = E;
}

__global__ void scatter(const int* __restrict__ ei, int E) {
    int i = blockIdx.x * blockDim.x + threadIdx.x;
    if (i >= E) return;
    int s = __ldg(&ei[i]);
    int d = __ldg(&ei[E + i]);
    int pos = g_rowptr[d] + atomicAdd(&g_deg[d], 1);
    g_csr_src[pos] = s;
}

// ============ persistent dual GEMM, W register-resident (bf16 x3) ==========
// 148 blocks x 512 threads (16 warps). warp w: matrix m = w>>3
// (0: xl, 1: xr), strip = cols [(w&7)*16, +16). W frags in registers.
// Chunk = 32 A rows; A register-double-buffered; direct fp32 stores.
using fA = wmma::fragment<wmma::matrix_a, 16, 16, 16, __nv_bfloat16, wmma::row_major>;
using fB = wmma::fragment<wmma::matrix_b, 16, 16, 16, __nv_bfloat16, wmma::row_major>;
using fC = wmma::fragment<wmma::accumulator, 16, 16, 16, float>;

__device__ __forceinline__ void cvt4(float4 v, __nv_bfloat16* hi, __nv_bfloat16* lo) {
    __nv_bfloat16 h0 = __float2bfloat16(v.x);
    __nv_bfloat16 h1 = __float2bfloat16(v.y);
    __nv_bfloat16 h2 = __float2bfloat16(v.z);
    __nv_bfloat16 h3 = __float2bfloat16(v.w);
    hi[0] = h0; hi[1] = h1; hi[2] = h2; hi[3] = h3;
    lo[0] = __float2bfloat16(v.x - __bfloat162float(h0));
    lo[1] = __float2bfloat16(v.y - __bfloat162float(h1));
    lo[2] = __float2bfloat16(v.z - __bfloat162float(h2));
    lo[3] = __float2bfloat16(v.w - __bfloat162float(h3));
}

__global__ void __launch_bounds__(512, 1)
dual_gemm_wreg(const float* __restrict__ Aext,
               const float* __restrict__ Wl,
               const float* __restrict__ Wr,
               int useH, int n) {
    // union region (34816B): W staging 128xSW bf16 / A hi+lo 2x32xSW bf16
    __shared__ __align__(16) unsigned char smem_u[34816];
    __nv_bfloat16* ws   = (__nv_bfloat16*)smem_u;
    __nv_bfloat16* ah_s = (__nv_bfloat16*)smem_u;
    __nv_bfloat16* al_s = ah_s + 32 * SW;

    const float* A = useH ? g_h : Aext;
    const float* Wmat[2] = {Wl, Wr};
    int tid   = threadIdx.x;
    int warp  = tid >> 5;
    int mat   = warp >> 3;          // 0 = xl, 1 = xr
    int sbase = (warp & 7) * 16;    // this warp's 16-col strip

    // per-thread A slot: f = tid + t*512 -> row rA[t], col cA[t]
    int r0A = tid >> 5,          c0A = (tid & 31) * 4;
    int r1A = (tid + 512) >> 5,  c1A = (tid & 31) * 4;

    // ---- load W fragments into registers (4 staging passes) ----
    fB wf[2][8];                    // [part][k]
    #pragma unroll
    for (int m = 0; m < 2; ++m) {
        #pragma unroll
        for (int part = 0; part < 2; ++part) {
            __syncthreads();
            #pragma unroll
            for (int t = 0; t < 8; ++t) {
                int f  = tid + t * 512;
                int r  = f >> 5;
                int c4 = (f & 31) * 4;
                float4 v = *(const float4*)&Wmat[m][(size_t)r * 128 + c4];
                __nv_bfloat16 b0 = __float2bfloat16(v.x);
                __nv_bfloat16 b1 = __float2bfloat16(v.y);
                __nv_bfloat16 b2 = __float2bfloat16(v.z);
                __nv_bfloat16 b3 = __float2bfloat16(v.w);
                __nv_bfloat16* dst = &ws[r * SW + c4];
                if (part == 0) {
                    dst[0] = b0; dst[1] = b1; dst[2] = b2; dst[3] = b3;
                } else {
                    dst[0] = __float2bfloat16(v.x - __bfloat162float(b0));
                    dst[1] = __float2bfloat16(v.y - __bfloat162float(b1));
                    dst[2] = __float2bfloat16(v.z - __bfloat162float(b2));
                    dst[3] = __float2bfloat16(v.w - __bfloat162float(b3));
                }
            }
            __syncthreads();
            if (mat == m) {
                #pragma unroll
                for (int k = 0; k < 8; ++k)
                    wmma::load_matrix_sync(wf[part][k],
                                           &ws[k * 16 * SW + sbase], SW);
            }
        }
    }

    float* C = mat ? g_xr : g_xl;
    int nchunks = (n + 31) >> 5;

    // preload first chunk's A into registers
    int c = blockIdx.x;
    float4 rv0 = make_float4(0.f, 0.f, 0.f, 0.f);
    float4 rv1 = make_float4(0.f, 0.f, 0.f, 0.f);
    if (c < nchunks) {
        int row0 = c * 32;
        if (row0 + r0A < n) rv0 = *(const float4*)&A[(size_t)(row0 + r0A) * 128 + c0A];
        if (row0 + r1A < n) rv1 = *(const float4*)&A[(size_t)(row0 + r1A) * 128 + c1A];
    }

    for (; c < nchunks; c += gridDim.x) {
        int row0 = c * 32;
        __syncthreads();              // smem free (W setup / prev MMA reads done)
        cvt4(rv0, &ah_s[r0A * SW + c0A], &al_s[r0A * SW + c0A]);
        cvt4(rv1, &ah_s[r1A * SW + c1A], &al_s[r1A * SW + c1A]);
        __syncthreads();

        // prefetch next chunk's A (completes under the MMA phase)
        int cn = c + gridDim.x;
        rv0 = make_float4(0.f, 0.f, 0.f, 0.f);
        rv1 = make_float4(0.f, 0.f, 0.f, 0.f);
        if (cn < nchunks) {
            int rown = cn * 32;
            if (rown + r0A < n) rv0 = *(const float4*)&A[(size_t)(rown + r0A) * 128 + c0A];
            if (rown + r1A < n) rv1 = *(const float4*)&A[(size_t)(rown + r1A) * 128 + c1A];
        }

        fC acc[2];
        wmma::fill_fragment(acc[0], 0.0f);
        wmma::fill_fragment(acc[1], 0.0f);

        #pragma unroll
        for (int k = 0; k < 8; ++k) {
            fA ah[2], al[2];
            wmma::load_matrix_sync(ah[0], &ah_s[0 * SW + k * 16], SW);
            wmma::load_matrix_sync(ah[1], &ah_s[16 * SW + k * 16], SW);
            wmma::load_matrix_sync(al[0], &al_s[0 * SW + k * 16], SW);
            wmma::load_matrix_sync(al[1], &al_s[16 * SW + k * 16], SW);
            wmma::mma_sync(acc[0], ah[0], wf[0][k], acc[0]);
            wmma::mma_sync(acc[1], ah[1], wf[0][k], acc[1]);
            wmma::mma_sync(acc[0], ah[0], wf[1][k], acc[0]);
            wmma::mma_sync(acc[1], ah[1], wf[1][k], acc[1]);
            wmma::mma_sync(acc[0], al[0], wf[0][k], acc[0]);
            wmma::mma_sync(acc[1], al[1], wf[0][k], acc[1]);
        }

        // direct fp32 stores (no smem involved)
        #pragma unroll
        for (int rt = 0; rt < 2; ++rt) {
            int wrow0 = row0 + rt * 16;
            if (wrow0 < n)
                wmma::store_matrix_sync(&C[(size_t)wrow0 * 128 + sbase],
                                        acc[rt], 128, wmma::mem_row_major);
        }
    }
}

// ================= fused GAT layer: warp per dst node ======================
__device__ __forceinline__ float edge_p(float4 l4, float4 r4, float4 a4) {
    float v0 = l4.x + r4.x; v0 = v0 > 0.f ? v0 : 0.2f * v0;
    float v1 = l4.y + r4.y; v1 = v1 > 0.f ? v1 : 0.2f * v1;
    float v2 = l4.z + r4.z; v2 = v2 > 0.f ? v2 : 0.2f * v2;
    float v3 = l4.w + r4.w; v3 = v3 > 0.f ? v3 : 0.2f * v3;
    float part = v0 * a4.x + v1 * a4.y + v2 * a4.z + v3 * a4.w;
    part += __shfl_xor_sync(0xffffffffu, part, 1);
    part += __shfl_xor_sync(0xffffffffu, part, 2);
    return __expf(part);
}

__global__ void gat_layer(const float* __restrict__ att,
                          const float* __restrict__ bias,
                          int doRelu, int n) {
    int d = blockIdx.x * 8 + (threadIdx.x >> 5);
    if (d >= n) return;
    int lane = threadIdx.x & 31;

    float4 a4 = *(const float4*)&att[lane * 4];
    float4 r4 = *(const float4*)&g_xr[(size_t)d * 128 + lane * 4];

    float4 l4 = *(const float4*)&g_xl[(size_t)d * 128 + lane * 4];
    float p = edge_p(l4, r4, a4);
    float4 acc = make_float4(p * l4.x, p * l4.y, p * l4.z, p * l4.w);
    float den = p;

    int e   = g_rowptr[d];
    int end = g_rowptr[d + 1];

    for (; e + 3 < end; e += 4) {
        int s0 = __ldg(&g_csr_src[e]);
        int s1 = __ldg(&g_csr_src[e + 1]);
        int s2 = __ldg(&g_csr_src[e + 2]);
        int s3 = __ldg(&g_csr_src[e + 3]);
        float4 u0 = *(const float4*)&g_xl[(size_t)s0 * 128 + lane * 4];
        float4 u1 = *(const float4*)&g_xl[(size_t)s1 * 128 + lane * 4];
        float4 u2 = *(const float4*)&g_xl[(size_t)s2 * 128 + lane * 4];
        float4 u3 = *(const float4*)&g_xl[(size_t)s3 * 128 + lane * 4];
        float p0 = edge_p(u0, r4, a4);
        float p1 = edge_p(u1, r4, a4);
        float p2 = edge_p(u2, r4, a4);
        float p3 = edge_p(u3, r4, a4);
        acc.x += p0 * u0.x + p1 * u1.x + p2 * u2.x + p3 * u3.x;
        acc.y += p0 * u0.y + p1 * u1.y + p2 * u2.y + p3 * u3.y;
        acc.z += p0 * u0.z + p1 * u1.z + p2 * u2.z + p3 * u3.z;
        acc.w += p0 * u0.w + p1 * u1.w + p2 * u2.w + p3 * u3.w;
        den += p0 + p1 + p2 + p3;
    }
    for (; e < end; ++e) {
        int s0 = __ldg(&g_csr_src[e]);
        float4 u0 = *(const float4*)&g_xl[(size_t)s0 * 128 + lane * 4];
        float p0 = edge_p(u0, r4, a4);
        acc.x += p0 * u0.x; acc.y += p0 * u0.y;
        acc.z += p0 * u0.z; acc.w += p0 * u0.w;
        den += p0;
    }

    float inv = 1.0f / (den + 1e-16f);
    float4 b4 = bias ? *(const float4*)&bias[lane * 4]
                     : make_float4(0.f, 0.f, 0.f, 0.f);
    float4 o;
    o.x = acc.x * inv + b4.x;
    o.y = acc.y * inv + b4.y;
    o.z = acc.z * inv + b4.z;
    o.w = acc.w * inv + b4.w;
    if (doRelu) {
        o.x = o.x > 0.f ? o.x : 0.f;
        o.y = o.y > 0.f ? o.y : 0.f;
        o.z = o.z > 0.f ? o.z : 0.f;
        o.w = o.w > 0.f ? o.w : 0.f;
    }
    *(float4*)&g_h[(size_t)d * 128 + lane * 4] = o;
}

// ================= final fc: out = relu(g_h + b2) @ Wfc + bfc ==============
__global__ void fc_out(const float* __restrict__ Wfc,
                       const float* __restrict__ bfc,
                       const float* __restrict__ b2,
                       float* __restrict__ out, int n) {
    __shared__ float Ws[128 * 10];
    __shared__ float bs[10];
    __shared__ float b2s[128];
    for (int i = threadIdx.x; i < 1280; i += blockDim.x) Ws[i] = Wfc[i];
    if (threadIdx.x < 10)  bs[threadIdx.x]  = bfc[threadIdx.x];
    if (threadIdx.x < 128) b2s[threadIdx.x] = b2[threadIdx.x];
    __syncthreads();
    int idx = blockIdx.x * blockDim.x + threadIdx.x;
    if (idx >= n * 10) return;
    int node = idx / 10;
    int c    = idx % 10;
    const float* hrow = &g_h[(size_t)node * 128];
    float acc = bs[c];
    #pragma unroll
    for (int k = 0; k < 128; ++k) {
        float hv = hrow[k] + b2s[k];
        hv = hv > 0.f ? hv : 0.f;
        acc += hv * Ws[k * 10 + c];
    }
    out[idx] = acc;
}

// ================= launch ==================================================
extern "C" void kernel_launch(void* const* d_in, const int* in_sizes, int n_in,
                              void* d_out, int out_size) {
    const float* x    = (const float*)d_in[0];
    const int*   ei   = (const int*)  d_in[1];
    const float* Wl1  = (const float*)d_in[2];
    const float* Wr1  = (const float*)d_in[3];
    const float* att1 = (const float*)d_in[4];
    const float* b1   = (const float*)d_in[5];
    const float* Wl2  = (const float*)d_in[6];
    const float* Wr2  = (const float*)d_in[7];
    const float* att2 = (const float*)d_in[8];
    const float* b2   = (const float*)d_in[9];
    const float* Wfc  = (const float*)d_in[10];
    const float* bfc  = (const float*)d_in[11];
    float* out = (float*)d_out;

    int n = in_sizes[0] / 128;
    int E = in_sizes[1] / 2;

    int nb_scan    = (n + 1023) / 1024;
    int gat_blocks = (n + 7) / 8;
    int fc_blocks  = (n * 10 + 255) / 256;
    int e_blocks   = (E + 255) / 256;
    int n_blocks   = (n + 255) / 256;

    static int inited = 0;
    static cudaStream_t s_csr;
    static cudaEvent_t  ev_fork, ev_join;
    if (!inited) {
        cudaStreamCreateWithFlags(&s_csr, cudaStreamNonBlocking);
        cudaEventCreateWithFlags(&ev_fork, cudaEventDisableTiming);
        cudaEventCreateWithFlags(&ev_join, cudaEventDisableTiming);
        inited = 1;
    }

    // ---- fork: CSR build (s_csr)  ||  layer-1 GEMM (default) ----
    // (dual_gemm submitted 4th so the ncu slot profiles it)
    cudaEventRecord(ev_fork, 0);
    cudaStreamWaitEvent(s_csr, ev_fork, 0);

    deg_zero<<<n_blocks, 256, 0, s_csr>>>(n);
    deg_count<<<e_blocks, 256, 0, s_csr>>>(ei, E);
    scan1<<<nb_scan, 1024, 0, s_csr>>>(n);

    dual_gemm_wreg<<<NSM, 512>>>(x, Wl1, Wr1, 0, n);   // 4th submission

    scan3<<<n_blocks, 256, 0, s_csr>>>(n, E, nb_scan);
    scatter<<<e_blocks, 256, 0, s_csr>>>(ei, E);
    cudaEventRecord(ev_join, s_csr);

    cudaStreamWaitEvent(0, ev_join, 0);

    // ---- layer 1 ----
    gat_layer<<<gat_blocks, 256>>>(att1, b1, 1, n);

    // ---- layer 2 ----
    dual_gemm_wreg<<<NSM, 512>>>(nullptr, Wl2, Wr2, 1, n);
    gat_layer<<<gat_blocks, 256>>>(att2, nullptr, 0, n);

    // ---- fc ----
    fc_out<<<fc_blocks, 256>>>(Wfc, bfc, b2, out, n);
}